// round 4
// baseline (speedup 1.0000x reference)
#include <cuda_runtime.h>

#define BB   2
#define CC   256
#define NH   8
#define DD   32
#define NWIN 256
#define TQ   16
#define LL   64
#define LM   1024
#define LG   256

// ---------- device scratch ----------
__device__ __align__(16) float g_qtok[BB*NWIN*TQ*CC];
__device__ __align__(16) float g_q   [BB*NWIN*TQ*CC];
__device__ __align__(16) float g_pt  [CC*(BB*LM + BB*LG)];   // column-major [C][2560]
__device__ __align__(16) float g_kl  [BB*NWIN*NH*DD*LL];
__device__ __align__(16) float g_vl  [BB*NWIN*NH*LL*DD];
__device__ __align__(16) float g_km  [BB*NH*DD*LM];
__device__ __align__(16) float g_vm  [BB*NH*LM*DD];
__device__ __align__(16) float g_kg  [BB*NH*DD*LG];
__device__ __align__(16) float g_vg  [BB*NH*LG*DD];
__device__ __align__(16) float g_o   [BB*NWIN*TQ*CC];

// ---------- kernel 1: window scramble + LayerNorm (one warp per token) ----------
__global__ void ln_qtok_kernel(const float* __restrict__ feat,
                               const float* __restrict__ lnw,
                               const float* __restrict__ lnb) {
    int gw   = (blockIdx.x * blockDim.x + threadIdx.x) >> 5;
    int lane = threadIdx.x & 31;
    if (gw >= BB*NWIN*TQ) return;
    int t = gw & 15, w = (gw >> 4) & 255, b = gw >> 12;
    int wy = w >> 4, wx = w & 15;
    float v[8];
#pragma unroll
    for (int e = 0; e < 8; e++) {
        int cp = e*32 + lane;
        int c  = t*16 + (cp >> 4);
        int s  = cp & 15;
        int y  = wy*4 + (s >> 2), x = wx*4 + (s & 3);
        v[e] = feat[((b*CC + c) << 12) + (y << 6) + x];
    }
    float sum = 0.f, sq = 0.f;
#pragma unroll
    for (int e = 0; e < 8; e++) { sum += v[e]; sq += v[e]*v[e]; }
#pragma unroll
    for (int o = 16; o; o >>= 1) {
        sum += __shfl_xor_sync(0xffffffffu, sum, o);
        sq  += __shfl_xor_sync(0xffffffffu, sq,  o);
    }
    float mean = sum * (1.f/256.f);
    float var  = sq  * (1.f/256.f) - mean*mean;
    float rstd = rsqrtf(var + 1e-5f);
    float* dst = g_qtok + gw*CC;
#pragma unroll
    for (int e = 0; e < 8; e++) {
        int cp = e*32 + lane;
        dst[cp] = (v[e]-mean)*rstd*lnw[cp] + lnb[cp];
    }
}

// ---------- kernel 2: 2x2 + 4x4 avg pooling -> column-major token buffer ----------
__global__ void pool_kernel(const float* __restrict__ feat) {
    int idx = blockIdx.x * blockDim.x + threadIdx.x;   // 655360 = 256*2560
    int c = idx / 2560;
    int r = idx - c*2560;
    float val;
    if (r < BB*LM) {
        int b = r >> 10, tk = r & 1023;
        int ym = tk >> 5, xm = tk & 31;
        const float* p = feat + ((b*CC + c) << 12) + (ym << 7) + (xm << 1);
        val = 0.25f * (p[0] + p[1] + p[64] + p[65]);
    } else {
        int r2 = r - BB*LM;
        int b = r2 >> 8, tk = r2 & 255;
        int yg = tk >> 4, xg = tk & 15;
        const float* p = feat + ((b*CC + c) << 12) + (yg << 8) + (xg << 2);
        float s = 0.f;
#pragma unroll
        for (int dy = 0; dy < 4; dy++)
#pragma unroll
            for (int dx = 0; dx < 4; dx++)
                s += p[dy*64 + dx];
        val = s * (1.f/16.f);
    }
    g_pt[c*2560 + r] = val;
}

// ---------- SGEMM 128x128x8, 256 threads, 8x8/thread ----------
// MODE 0: local KV (A gathered from padded features), 1: Q proj, 2: pooled KV, 3: out proj
template<int MODE>
__global__ void __launch_bounds__(256) gemm_kernel(const float* __restrict__ Wm,
                                                   const float* __restrict__ bias,
                                                   const float* __restrict__ feat,
                                                   float* __restrict__ dout) {
    __shared__ __align__(16) float As[8][128];
    __shared__ __align__(16) float Bs[8][128];
    const int tid  = threadIdx.x;
    const int bcol = blockIdx.x, brow = blockIdx.y;
    const int tx = tid & 15, ty = tid >> 4;
    constexpr int LDB  = (MODE == 3) ? 256 : 768;
    constexpr int COL0 = (MODE == 0 || MODE == 2) ? 256 : 0;
    const int m0 = brow * 128;
    const int arow = tid >> 1;
    const int ak4  = (tid & 1) << 2;

    float acc[8][8];
#pragma unroll
    for (int i = 0; i < 8; i++)
#pragma unroll
        for (int j = 0; j < 8; j++) acc[i][j] = 0.f;

    int gw_b = 0, gw_wy = 0, gw_wx = 0, gw_l = 0;
    if constexpr (MODE == 0) {
        int row = m0 + arow;
        gw_b = row >> 14;
        int rem = row & 16383;
        int w  = rem >> 6;
        gw_l  = rem & 63;
        gw_wy = w >> 4; gw_wx = w & 15;
    }

    for (int k0 = 0; k0 < 256; k0 += 8) {
        {   // B tile 8x128 coalesced
            int bk = tid >> 5, bn = (tid & 31) << 2;
            float4 bv = *reinterpret_cast<const float4*>(Wm + (k0+bk)*LDB + COL0 + bcol*128 + bn);
            *reinterpret_cast<float4*>(&Bs[bk][bn]) = bv;
        }
        if constexpr (MODE == 2) {
            int bk = tid >> 5, am = (tid & 31) << 2;
            float4 av = *reinterpret_cast<const float4*>(g_pt + (k0+bk)*2560 + m0 + am);
            *reinterpret_cast<float4*>(&As[bk][am]) = av;
        } else if constexpr (MODE == 0) {
#pragma unroll
            for (int i = 0; i < 4; i++) {
                int cp = k0 + ak4 + i;
                int c  = gw_l*4 + (cp >> 6);
                int s  = cp & 63;
                int y  = gw_wy*4 + (s >> 3) - 2;
                int x  = gw_wx*4 + (s & 7)  - 2;
                float v = 0.f;
                if ((unsigned)y < 64u && (unsigned)x < 64u)
                    v = feat[((gw_b*CC + c) << 12) + (y << 6) + x];
                As[ak4+i][arow] = v;
            }
        } else {
            const float* Aptr = (MODE == 1) ? g_qtok : g_o;
            float4 av = *reinterpret_cast<const float4*>(Aptr + (m0+arow)*256 + k0 + ak4);
            As[ak4+0][arow] = av.x; As[ak4+1][arow] = av.y;
            As[ak4+2][arow] = av.z; As[ak4+3][arow] = av.w;
        }
        __syncthreads();
#pragma unroll
        for (int kk = 0; kk < 8; kk++) {
            float4 a0 = *reinterpret_cast<const float4*>(&As[kk][ty*8]);
            float4 a1 = *reinterpret_cast<const float4*>(&As[kk][ty*8+4]);
            float4 b0 = *reinterpret_cast<const float4*>(&Bs[kk][tx*8]);
            float4 b1 = *reinterpret_cast<const float4*>(&Bs[kk][tx*8+4]);
            float ar[8] = {a0.x,a0.y,a0.z,a0.w,a1.x,a1.y,a1.z,a1.w};
            float br[8] = {b0.x,b0.y,b0.z,b0.w,b1.x,b1.y,b1.z,b1.w};
#pragma unroll
            for (int i = 0; i < 8; i++)
#pragma unroll
                for (int j = 0; j < 8; j++)
                    acc[i][j] = fmaf(ar[i], br[j], acc[i][j]);
        }
        __syncthreads();
    }

#pragma unroll
    for (int i = 0; i < 8; i++) {
        int m = m0 + ty*8 + i;
#pragma unroll
        for (int j = 0; j < 8; j++) {
            int n = bcol*128 + tx*8 + j;
            float val = acc[i][j];
            if constexpr (MODE == 0) {
                val += bias[256 + n];
                int b = m >> 14, rem = m & 16383;
                int w = rem >> 6, l = rem & 63;
                if (n < 256) {
                    int h = n >> 5, d = n & 31;
                    g_kl[(((b*NWIN + w)*NH + h)*DD + d)*LL + l] = val;
                } else {
                    int n2 = n - 256, h = n2 >> 5, d = n2 & 31;
                    g_vl[(((b*NWIN + w)*NH + h)*LL + l)*DD + d] = val;
                }
            } else if constexpr (MODE == 1) {
                g_q[m*256 + n] = val + bias[n];
            } else if constexpr (MODE == 2) {
                val += bias[256 + n];
                if (m < BB*LM) {
                    int b = m >> 10, tk = m & 1023;
                    if (n < 256) { int h=n>>5, d=n&31; g_km[((b*NH+h)*DD+d)*LM + tk] = val; }
                    else { int n2=n-256, h=n2>>5, d=n2&31; g_vm[((b*NH+h)*LM+tk)*DD + d] = val; }
                } else {
                    int m2 = m - BB*LM;
                    int b = m2 >> 8, tk = m2 & 255;
                    if (n < 256) { int h=n>>5, d=n&31; g_kg[((b*NH+h)*DD+d)*LG + tk] = val; }
                    else { int n2=n-256, h=n2>>5, d=n2&31; g_vg[((b*NH+h)*LG+tk)*DD + d] = val; }
                }
            } else {
                val += bias[n];
                int b = m >> 12, rem = m & 4095;
                int w = rem >> 4, t = rem & 15;
                int y = (w >> 4)*4 + (t >> 2);
                int x = (w & 15)*4 + (t & 3);
                int idx = ((b*CC + n) << 12) + (y << 6) + x;
                dout[idx] = val + feat[idx];
            }
        }
    }
}

// ---------- fused flash attention: 1 CTA per (w,h,b), 128 threads, 11 chunks ----------
__global__ void __launch_bounds__(128) attn_kernel() {
    const int w = blockIdx.x, h = blockIdx.y, b = blockIdx.z;
    const int tid = threadIdx.x;
    const int lane = tid & 31, wrp = tid >> 5;
    __shared__ __align__(16) float qs [16*32];
    __shared__ __align__(16) float Ssm[16*132];
    __shared__ __align__(16) float Vs [128*36];
    __shared__ float red_max[4*16], red_sum[4*16];
    __shared__ float mS[16], lS[16], scaleS[16];

    {   // q tile, pre-scaled by 1/sqrt(d)
        int t = tid >> 3, jv = tid & 7;
        float4 qv = reinterpret_cast<const float4*>(g_q + ((b*NWIN+w)*TQ + t)*CC + h*DD)[jv];
        const float sc = 0.1767766952966369f;
        qv.x *= sc; qv.y *= sc; qv.z *= sc; qv.w *= sc;
        reinterpret_cast<float4*>(qs)[tid] = qv;
    }
    if (tid < 16) { mS[tid] = -1e30f; lS[tid] = 0.f; }

    float oacc[4] = {0.f, 0.f, 0.f, 0.f};
    const int pq = tid >> 3, pjg = tid & 7;

    for (int ch = 0; ch < 11; ch++) {
        const float* Kp; const float* Vp; int Lk, kbase, cn;
        if (ch == 0) {
            Kp = g_kl + (((b*NWIN + w)*NH + h)*DD)*LL;
            Vp = g_vl + (((b*NWIN + w)*NH + h)*LL)*DD;
            Lk = LL; kbase = 0; cn = 64;
        } else if (ch <= 8) {
            Kp = g_km + ((b*NH + h)*DD)*LM;
            Vp = g_vm + ((b*NH + h)*LM)*DD;
            Lk = LM; kbase = (ch-1)*128; cn = 128;
        } else {
            Kp = g_kg + ((b*NH + h)*DD)*LG;
            Vp = g_vg + ((b*NH + h)*LG)*DD;
            Lk = LG; kbase = (ch-9)*128; cn = 128;
        }

        __syncthreads();   // prior PV done consuming S/Vs/scaleS; mS/lS/qs visible

        // scores: one key per thread, q broadcast from smem
        float s[16];
        if (tid < cn) {
            float kreg[32];
#pragma unroll
            for (int j = 0; j < 32; j++) kreg[j] = Kp[j*Lk + kbase + tid];
#pragma unroll
            for (int q = 0; q < 16; q++) {
                float a = 0.f;
#pragma unroll
                for (int jv = 0; jv < 8; jv++) {
                    float4 qv = reinterpret_cast<const float4*>(qs)[q*8 + jv];
                    a = fmaf(qv.x, kreg[jv*4+0], a);
                    a = fmaf(qv.y, kreg[jv*4+1], a);
                    a = fmaf(qv.z, kreg[jv*4+2], a);
                    a = fmaf(qv.w, kreg[jv*4+3], a);
                }
                s[q] = a;
            }
        } else {
#pragma unroll
            for (int q = 0; q < 16; q++) s[q] = -1e30f;
        }

        // per-warp max
#pragma unroll
        for (int q = 0; q < 16; q++) {
            float m = s[q];
#pragma unroll
            for (int o = 16; o; o >>= 1) m = fmaxf(m, __shfl_xor_sync(0xffffffffu, m, o));
            if (lane == 0) red_max[wrp*16 + q] = m;
        }

        // stage V chunk into padded smem [kk][d]
        {
            const float4* V4 = reinterpret_cast<const float4*>(Vp + kbase*DD);
#pragma unroll
            for (int i = 0; i < 8; i++) {
                int e  = tid + i*128;
                int kk = e >> 3, jv = e & 7;
                float4 v;
                if (kk < cn) v = V4[kk*8 + jv];
                else         v = make_float4(0.f, 0.f, 0.f, 0.f);
                reinterpret_cast<float4*>(Vs)[kk*9 + jv] = v;
            }
        }

        __syncthreads();   // red_max + Vs visible

        // online softmax
        float m_new[16], sm[16];
#pragma unroll
        for (int q = 0; q < 16; q++) {
            float cmax = fmaxf(fmaxf(red_max[q], red_max[16+q]),
                               fmaxf(red_max[32+q], red_max[48+q]));
            float mo = mS[q];
            float mn = fmaxf(mo, cmax);
            m_new[q] = mn;
            float p = __expf(s[q] - mn);
            Ssm[q*132 + tid] = p;
            sm[q] = p;
            if (tid == q) scaleS[q] = __expf(mo - mn);
        }
#pragma unroll
        for (int q = 0; q < 16; q++) {
            float su = sm[q];
#pragma unroll
            for (int o = 16; o; o >>= 1) su += __shfl_xor_sync(0xffffffffu, su, o);
            if (lane == 0) red_sum[wrp*16 + q] = su;
        }

        __syncthreads();   // Ssm, scaleS, red_sum visible

        if (tid < 16) {
            int q = tid;
            float cs = red_sum[q] + red_sum[16+q] + red_sum[32+q] + red_sum[48+q];
            lS[q] = lS[q]*scaleS[q] + cs;
            mS[q] = m_new[q];
        }

        // PV: oacc[pq][pjg*4..+3] update
        {
            float scl = scaleS[pq];
            oacc[0] *= scl; oacc[1] *= scl; oacc[2] *= scl; oacc[3] *= scl;
            const float4* S4 = reinterpret_cast<const float4*>(Ssm) + pq*33;
            const float4* Vv = reinterpret_cast<const float4*>(Vs);
#pragma unroll 4
            for (int k4 = 0; k4 < 32; k4++) {
                float4 p = S4[k4];
                float4 v;
                v = Vv[(k4*4+0)*9 + pjg];
                oacc[0]=fmaf(p.x,v.x,oacc[0]); oacc[1]=fmaf(p.x,v.y,oacc[1]);
                oacc[2]=fmaf(p.x,v.z,oacc[2]); oacc[3]=fmaf(p.x,v.w,oacc[3]);
                v = Vv[(k4*4+1)*9 + pjg];
                oacc[0]=fmaf(p.y,v.x,oacc[0]); oacc[1]=fmaf(p.y,v.y,oacc[1]);
                oacc[2]=fmaf(p.y,v.z,oacc[2]); oacc[3]=fmaf(p.y,v.w,oacc[3]);
                v = Vv[(k4*4+2)*9 + pjg];
                oacc[0]=fmaf(p.z,v.x,oacc[0]); oacc[1]=fmaf(p.z,v.y,oacc[1]);
                oacc[2]=fmaf(p.z,v.z,oacc[2]); oacc[3]=fmaf(p.z,v.w,oacc[3]);
                v = Vv[(k4*4+3)*9 + pjg];
                oacc[0]=fmaf(p.w,v.x,oacc[0]); oacc[1]=fmaf(p.w,v.y,oacc[1]);
                oacc[2]=fmaf(p.w,v.z,oacc[2]); oacc[3]=fmaf(p.w,v.w,oacc[3]);
            }
        }
    }

    __syncthreads();
    float inv = 1.f / lS[pq];
    float4 ov = make_float4(oacc[0]*inv, oacc[1]*inv, oacc[2]*inv, oacc[3]*inv);
    reinterpret_cast<float4*>(g_o + ((b*NWIN+w)*TQ + pq)*CC + h*DD)[pjg] = ov;
}

extern "C" void kernel_launch(void* const* d_in, const int* in_sizes, int n_in,
                              void* d_out, int out_size) {
    const float* feat  = (const float*)d_in[0];
    const float* qkv_w = (const float*)d_in[1];
    const float* qkv_b = (const float*)d_in[2];
    const float* out_w = (const float*)d_in[3];
    const float* out_b = (const float*)d_in[4];
    const float* ln_w  = (const float*)d_in[5];
    const float* ln_b  = (const float*)d_in[6];
    float* out = (float*)d_out;

    ln_qtok_kernel<<<1024, 256>>>(feat, ln_w, ln_b);
    pool_kernel<<<2560, 256>>>(feat);
    gemm_kernel<0><<<dim3(4, 256), 256>>>(qkv_w, qkv_b, feat, nullptr);  // local KV
    gemm_kernel<1><<<dim3(2, 64),  256>>>(qkv_w, qkv_b, feat, nullptr);  // Q proj
    gemm_kernel<2><<<dim3(4, 20),  256>>>(qkv_w, qkv_b, feat, nullptr);  // pooled KV
    attn_kernel<<<dim3(256, 8, 2), 128>>>();
    gemm_kernel<3><<<dim3(2, 64),  256>>>(out_w, out_b, feat, out);      // out proj + residual
}

// round 8
// speedup vs baseline: 1.0135x; 1.0135x over previous
#include <cuda_runtime.h>

typedef unsigned long long ull;

#define BB   2
#define CC   256
#define NH   8
#define DD   32
#define NWIN 256
#define TQ   16
#define LL   64
#define LM   1024
#define LG   256

// ---------- packed f32x2 helpers (FFMA2 path, sm_103a) ----------
__device__ __forceinline__ ull pack2f(float x, float y) {
    ull d;
    asm("mov.b64 %0, {%1, %2};" : "=l"(d)
        : "r"(__float_as_uint(x)), "r"(__float_as_uint(y)));
    return d;
}
__device__ __forceinline__ ull pack1f(float x) { return pack2f(x, x); }
__device__ __forceinline__ ull fma2(ull a, ull b, ull c) {
    ull d;
    asm("fma.rn.f32x2 %0, %1, %2, %3;" : "=l"(d) : "l"(a), "l"(b), "l"(c));
    return d;
}
__device__ __forceinline__ ull mul2(ull a, ull b) {
    ull d;
    asm("mul.rn.f32x2 %0, %1, %2;" : "=l"(d) : "l"(a), "l"(b));
    return d;
}
__device__ __forceinline__ void unpack2f(ull v, float& x, float& y) {
    unsigned lo, hi;
    asm("mov.b64 {%0, %1}, %2;" : "=r"(lo), "=r"(hi) : "l"(v));
    x = __uint_as_float(lo); y = __uint_as_float(hi);
}

// ---------- device scratch ----------
__device__ __align__(16) float g_qtok[BB*NWIN*TQ*CC];
__device__ __align__(16) float g_q   [BB*NWIN*TQ*CC];
__device__ __align__(16) float g_pt  [CC*(BB*LM + BB*LG)];   // column-major [C][2560]
__device__ __align__(16) float g_kl  [BB*NWIN*NH*DD*LL];
__device__ __align__(16) float g_vl  [BB*NWIN*NH*LL*DD];
__device__ __align__(16) float g_km  [BB*NH*DD*LM];
__device__ __align__(16) float g_vm  [BB*NH*LM*DD];
__device__ __align__(16) float g_kg  [BB*NH*DD*LG];
__device__ __align__(16) float g_vg  [BB*NH*LG*DD];
__device__ __align__(16) float g_o   [BB*NWIN*TQ*CC];

// ---------- kernel 1: window scramble + LayerNorm (one warp per token) ----------
__global__ void ln_qtok_kernel(const float* __restrict__ feat,
                               const float* __restrict__ lnw,
                               const float* __restrict__ lnb) {
    int gw   = (blockIdx.x * blockDim.x + threadIdx.x) >> 5;
    int lane = threadIdx.x & 31;
    if (gw >= BB*NWIN*TQ) return;
    int t = gw & 15, w = (gw >> 4) & 255, b = gw >> 12;
    int wy = w >> 4, wx = w & 15;
    float v[8];
#pragma unroll
    for (int e = 0; e < 8; e++) {
        int cp = e*32 + lane;
        int c  = t*16 + (cp >> 4);
        int s  = cp & 15;
        int y  = wy*4 + (s >> 2), x = wx*4 + (s & 3);
        v[e] = feat[((b*CC + c) << 12) + (y << 6) + x];
    }
    float sum = 0.f, sq = 0.f;
#pragma unroll
    for (int e = 0; e < 8; e++) { sum += v[e]; sq += v[e]*v[e]; }
#pragma unroll
    for (int o = 16; o; o >>= 1) {
        sum += __shfl_xor_sync(0xffffffffu, sum, o);
        sq  += __shfl_xor_sync(0xffffffffu, sq,  o);
    }
    float mean = sum * (1.f/256.f);
    float var  = sq  * (1.f/256.f) - mean*mean;
    float rstd = rsqrtf(var + 1e-5f);
    float* dst = g_qtok + gw*CC;
#pragma unroll
    for (int e = 0; e < 8; e++) {
        int cp = e*32 + lane;
        dst[cp] = (v[e]-mean)*rstd*lnw[cp] + lnb[cp];
    }
}

// ---------- kernel 2: 2x2 + 4x4 avg pooling -> column-major token buffer ----------
__global__ void pool_kernel(const float* __restrict__ feat) {
    int idx = blockIdx.x * blockDim.x + threadIdx.x;   // 655360 = 256*2560
    int c = idx / 2560;
    int r = idx - c*2560;
    float val;
    if (r < BB*LM) {
        int b = r >> 10, tk = r & 1023;
        int ym = tk >> 5, xm = tk & 31;
        const float* p = feat + ((b*CC + c) << 12) + (ym << 7) + (xm << 1);
        val = 0.25f * (p[0] + p[1] + p[64] + p[65]);
    } else {
        int r2 = r - BB*LM;
        int b = r2 >> 8, tk = r2 & 255;
        int yg = tk >> 4, xg = tk & 15;
        const float* p = feat + ((b*CC + c) << 12) + (yg << 8) + (xg << 2);
        float s = 0.f;
#pragma unroll
        for (int dy = 0; dy < 4; dy++)
#pragma unroll
            for (int dx = 0; dx < 4; dx++)
                s += p[dy*64 + dx];
        val = s * (1.f/16.f);
    }
    g_pt[c*2560 + r] = val;
}

// ---------- SGEMM 128xNT x8, 256 threads, double-buffered, f32x2 FMAs ----------
// MODE 0: local KV (A gathered), NT=128.  1: Q proj.  2: pooled KV.  3: out proj. (NT=64)
template<int MODE, int NT>
__global__ void __launch_bounds__(256) gemm_kernel(const float* __restrict__ Wm,
                                                   const float* __restrict__ bias,
                                                   const float* __restrict__ feat,
                                                   float* __restrict__ dout) {
    __shared__ __align__(16) float As[8][128];
    __shared__ __align__(16) float Bs[8][NT];
    const int tid  = threadIdx.x;
    const int bcol = blockIdx.x, brow = blockIdx.y;
    const int tx = tid & 15, ty = tid >> 4;
    constexpr int LDB  = (MODE == 3) ? 256 : 768;
    constexpr int COL0 = (MODE == 0 || MODE == 2) ? 256 : 0;
    constexpr int JW = NT / 16;      // cols per thread (8 or 4)
    constexpr int JP = JW / 2;       // packed col-pairs
    const int m0 = brow * 128;
    const int arow = tid >> 1;
    const int ak4  = (tid & 1) << 2;
    const int bk   = tid >> 5;
    const int bn   = (NT == 128) ? ((tid & 31) << 2) : ((tid & 31) << 1);
    const int am2  = (tid & 31) << 2;   // MODE 2 A-load col

    ull acc2[8][JP];
#pragma unroll
    for (int i = 0; i < 8; i++)
#pragma unroll
        for (int p = 0; p < JP; p++) acc2[i][p] = 0ull;

    int gw_b = 0, gw_wy = 0, gw_wx = 0, gw_l = 0;
    if constexpr (MODE == 0) {
        int row = m0 + arow;
        gw_b = row >> 14;
        int rem = row & 16383;
        int w  = rem >> 6;
        gw_l  = rem & 63;
        gw_wy = w >> 4; gw_wx = w & 15;
    }

    float pa[4]; float pb[4];

    auto loadA = [&](int k0) {
        if constexpr (MODE == 2) {
            float4 av = *reinterpret_cast<const float4*>(g_pt + (k0+bk)*2560 + m0 + am2);
            pa[0]=av.x; pa[1]=av.y; pa[2]=av.z; pa[3]=av.w;
        } else if constexpr (MODE == 0) {
#pragma unroll
            for (int i = 0; i < 4; i++) {
                int cp = k0 + ak4 + i;
                int c  = gw_l*4 + (cp >> 6);
                int s  = cp & 63;
                int y  = gw_wy*4 + (s >> 3) - 2;
                int x  = gw_wx*4 + (s & 7)  - 2;
                float v = 0.f;
                if ((unsigned)y < 64u && (unsigned)x < 64u)
                    v = feat[((gw_b*CC + c) << 12) + (y << 6) + x];
                pa[i] = v;
            }
        } else {
            const float* Aptr = (MODE == 1) ? g_qtok : g_o;
            float4 av = *reinterpret_cast<const float4*>(Aptr + (m0+arow)*256 + k0 + ak4);
            pa[0]=av.x; pa[1]=av.y; pa[2]=av.z; pa[3]=av.w;
        }
    };
    auto loadB = [&](int k0) {
        if constexpr (NT == 128) {
            float4 bv = *reinterpret_cast<const float4*>(Wm + (k0+bk)*LDB + COL0 + bcol*128 + bn);
            pb[0]=bv.x; pb[1]=bv.y; pb[2]=bv.z; pb[3]=bv.w;
        } else {
            float2 bv = *reinterpret_cast<const float2*>(Wm + (k0+bk)*LDB + COL0 + bcol*64 + bn);
            pb[0]=bv.x; pb[1]=bv.y;
        }
    };

    loadA(0); loadB(0);
    for (int k0 = 0; k0 < 256; k0 += 8) {
        // stage prefetched tile into smem
        if constexpr (MODE == 2) {
            *reinterpret_cast<float4*>(&As[bk][am2]) = make_float4(pa[0],pa[1],pa[2],pa[3]);
        } else {
            As[ak4+0][arow]=pa[0]; As[ak4+1][arow]=pa[1];
            As[ak4+2][arow]=pa[2]; As[ak4+3][arow]=pa[3];
        }
        if constexpr (NT == 128) {
            *reinterpret_cast<float4*>(&Bs[bk][bn]) = make_float4(pb[0],pb[1],pb[2],pb[3]);
        } else {
            *reinterpret_cast<float2*>(&Bs[bk][bn]) = make_float2(pb[0],pb[1]);
        }
        __syncthreads();
        if (k0 < 248) { loadA(k0+8); loadB(k0+8); }   // overlapped with compute
#pragma unroll
        for (int kk = 0; kk < 8; kk++) {
            float4 a0 = *reinterpret_cast<const float4*>(&As[kk][ty*8]);
            float4 a1 = *reinterpret_cast<const float4*>(&As[kk][ty*8+4]);
            ull ad[8] = {pack1f(a0.x),pack1f(a0.y),pack1f(a0.z),pack1f(a0.w),
                         pack1f(a1.x),pack1f(a1.y),pack1f(a1.z),pack1f(a1.w)};
            ull bd[JP];
            if constexpr (NT == 128) {
                ulonglong2 b01 = *reinterpret_cast<const ulonglong2*>(&Bs[kk][tx*JW]);
                ulonglong2 b23 = *reinterpret_cast<const ulonglong2*>(&Bs[kk][tx*JW+4]);
                bd[0]=b01.x; bd[1]=b01.y; bd[2]=b23.x; bd[3]=b23.y;
            } else {
                ulonglong2 b01 = *reinterpret_cast<const ulonglong2*>(&Bs[kk][tx*JW]);
                bd[0]=b01.x; bd[1]=b01.y;
            }
#pragma unroll
            for (int i = 0; i < 8; i++)
#pragma unroll
                for (int p = 0; p < JP; p++)
                    acc2[i][p] = fma2(ad[i], bd[p], acc2[i][p]);
        }
        __syncthreads();
    }

#pragma unroll
    for (int i = 0; i < 8; i++) {
        int m = m0 + ty*8 + i;
#pragma unroll
        for (int p = 0; p < JP; p++) {
            float vv[2]; unpack2f(acc2[i][p], vv[0], vv[1]);
#pragma unroll
            for (int u = 0; u < 2; u++) {
                int n = bcol*NT + tx*JW + 2*p + u;
                float val = vv[u];
                if constexpr (MODE == 0) {
                    val += bias[256 + n];
                    int b = m >> 14, rem = m & 16383;
                    int w = rem >> 6, l = rem & 63;
                    if (n < 256) {
                        int h = n >> 5, d = n & 31;
                        g_kl[(((b*NWIN + w)*NH + h)*DD + d)*LL + l] = val;
                    } else {
                        int n2 = n - 256, h = n2 >> 5, d = n2 & 31;
                        g_vl[(((b*NWIN + w)*NH + h)*LL + l)*DD + d] = val;
                    }
                } else if constexpr (MODE == 1) {
                    g_q[m*256 + n] = val + bias[n];
                } else if constexpr (MODE == 2) {
                    val += bias[256 + n];
                    if (m < BB*LM) {
                        int b = m >> 10, tk = m & 1023;
                        if (n < 256) { int h=n>>5, d=n&31; g_km[((b*NH+h)*DD+d)*LM + tk] = val; }
                        else { int n2=n-256, h=n2>>5, d=n2&31; g_vm[((b*NH+h)*LM+tk)*DD + d] = val; }
                    } else {
                        int m2 = m - BB*LM;
                        int b = m2 >> 8, tk = m2 & 255;
                        if (n < 256) { int h=n>>5, d=n&31; g_kg[((b*NH+h)*DD+d)*LG + tk] = val; }
                        else { int n2=n-256, h=n2>>5, d=n2&31; g_vg[((b*NH+h)*LG+tk)*DD + d] = val; }
                    }
                } else {
                    val += bias[n];
                    int b = m >> 12, rem = m & 4095;
                    int w = rem >> 4, t = rem & 15;
                    int y = (w >> 4)*4 + (t >> 2);
                    int x = (w & 15)*4 + (t & 3);
                    int idx = ((b*CC + n) << 12) + (y << 6) + x;
                    dout[idx] = val + feat[idx];
                }
            }
        }
    }
}

// ---------- fused flash attention: 1 CTA per (w,h,b), 128 threads, 11 chunks ----------
__global__ void __launch_bounds__(128) attn_kernel() {
    const int w = blockIdx.x, h = blockIdx.y, b = blockIdx.z;
    const int tid = threadIdx.x;
    const int lane = tid & 31, wrp = tid >> 5;
    __shared__ __align__(16) float qs_t[32][16];     // transposed q: [d][q]
    __shared__ __align__(16) float Ssm[16*132];
    __shared__ __align__(16) float Vs [128*36];
    __shared__ float red_max[64], red_sum[64];
    __shared__ float mS[16], lS[16], scaleS[16];

    {   // q tile, pre-scaled by 1/sqrt(d), transposed to [d][q]
        int t = tid >> 3, jv = tid & 7;
        float4 qv = reinterpret_cast<const float4*>(g_q + ((b*NWIN+w)*TQ + t)*CC + h*DD)[jv];
        const float sc = 0.1767766952966369f;
        qs_t[jv*4+0][t] = qv.x*sc; qs_t[jv*4+1][t] = qv.y*sc;
        qs_t[jv*4+2][t] = qv.z*sc; qs_t[jv*4+3][t] = qv.w*sc;
    }
    if (tid < 16) { mS[tid] = -1e30f; lS[tid] = 0.f; }

    ull oacc2[2] = {0ull, 0ull};
    const int pq = tid >> 3, pjg = tid & 7;

    for (int ch = 0; ch < 11; ch++) {
        const float* Kp; const float* Vp; int Lk, kbase, cn;
        if (ch == 0) {
            Kp = g_kl + (((b*NWIN + w)*NH + h)*DD)*LL;
            Vp = g_vl + (((b*NWIN + w)*NH + h)*LL)*DD;
            Lk = LL; kbase = 0; cn = 64;
        } else if (ch <= 8) {
            Kp = g_km + ((b*NH + h)*DD)*LM;
            Vp = g_vm + ((b*NH + h)*LM)*DD;
            Lk = LM; kbase = (ch-1)*128; cn = 128;
        } else {
            Kp = g_kg + ((b*NH + h)*DD)*LG;
            Vp = g_vg + ((b*NH + h)*LG)*DD;
            Lk = LG; kbase = (ch-9)*128; cn = 128;
        }

        __syncthreads();   // prior PV done; qs_t/mS/lS visible on first iter

        // scores: one key per thread; packed over q-pairs (8 FFMA2 per d)
        float s[16];
        if (tid < cn) {
            float kreg[32];
#pragma unroll
            for (int j = 0; j < 32; j++) kreg[j] = Kp[j*Lk + kbase + tid];
            ull a2[8];
#pragma unroll
            for (int qp = 0; qp < 8; qp++) a2[qp] = 0ull;
#pragma unroll
            for (int d = 0; d < 32; d++) {
                ull kd2 = pack1f(kreg[d]);
                ulonglong2 qa = *reinterpret_cast<const ulonglong2*>(&qs_t[d][0]);
                ulonglong2 qb = *reinterpret_cast<const ulonglong2*>(&qs_t[d][4]);
                ulonglong2 qc = *reinterpret_cast<const ulonglong2*>(&qs_t[d][8]);
                ulonglong2 qd = *reinterpret_cast<const ulonglong2*>(&qs_t[d][12]);
                a2[0] = fma2(kd2, qa.x, a2[0]); a2[1] = fma2(kd2, qa.y, a2[1]);
                a2[2] = fma2(kd2, qb.x, a2[2]); a2[3] = fma2(kd2, qb.y, a2[3]);
                a2[4] = fma2(kd2, qc.x, a2[4]); a2[5] = fma2(kd2, qc.y, a2[5]);
                a2[6] = fma2(kd2, qd.x, a2[6]); a2[7] = fma2(kd2, qd.y, a2[7]);
            }
#pragma unroll
            for (int qp = 0; qp < 8; qp++) unpack2f(a2[qp], s[2*qp], s[2*qp+1]);
        } else {
#pragma unroll
            for (int q = 0; q < 16; q++) s[q] = -1e30f;
        }

        // per-warp max
#pragma unroll
        for (int q = 0; q < 16; q++) {
            float m = s[q];
#pragma unroll
            for (int o = 16; o; o >>= 1) m = fmaxf(m, __shfl_xor_sync(0xffffffffu, m, o));
            if (lane == 0) red_max[wrp*16 + q] = m;
        }

        // stage V chunk into padded smem [kk][d] (stride 36 floats)
        {
            const float4* V4 = reinterpret_cast<const float4*>(Vp + kbase*DD);
#pragma unroll
            for (int i = 0; i < 8; i++) {
                int e  = tid + i*128;
                int kk = e >> 3, jv = e & 7;
                float4 v;
                if (kk < cn) v = V4[kk*8 + jv];
                else         v = make_float4(0.f, 0.f, 0.f, 0.f);
                reinterpret_cast<float4*>(Vs)[kk*9 + jv] = v;
            }
        }

        __syncthreads();   // red_max + Vs visible

        // online softmax
        float m_new[16], sm[16];
#pragma unroll
        for (int q = 0; q < 16; q++) {
            float cmax = fmaxf(fmaxf(red_max[q], red_max[16+q]),
                               fmaxf(red_max[32+q], red_max[48+q]));
            float mo = mS[q];
            float mn = fmaxf(mo, cmax);
            m_new[q] = mn;
            float p = __expf(s[q] - mn);
            Ssm[q*132 + tid] = p;
            sm[q] = p;
            if (tid == q) scaleS[q] = __expf(mo - mn);
        }
#pragma unroll
        for (int q = 0; q < 16; q++) {
            float su = sm[q];
#pragma unroll
            for (int o = 16; o; o >>= 1) su += __shfl_xor_sync(0xffffffffu, su, o);
            if (lane == 0) red_sum[wrp*16 + q] = su;
        }

        __syncthreads();   // Ssm, scaleS, red_sum visible

        if (tid < 16) {
            int q = tid;
            float cs = red_sum[q] + red_sum[16+q] + red_sum[32+q] + red_sum[48+q];
            lS[q] = lS[q]*scaleS[q] + cs;
            mS[q] = m_new[q];
        }

        // PV: packed d-pairs; oacc2 covers d = pjg*4 .. pjg*4+3
        {
            float scl = scaleS[pq];
            ull scl2 = pack1f(scl);
            oacc2[0] = mul2(oacc2[0], scl2);
            oacc2[1] = mul2(oacc2[1], scl2);
            const float4* S4 = reinterpret_cast<const float4*>(Ssm) + pq*33;
#pragma unroll 4
            for (int k4 = 0; k4 < 32; k4++) {
                float4 p = S4[k4];
                {
                    ulonglong2 v = *reinterpret_cast<const ulonglong2*>(&Vs[(k4*4+0)*36 + pjg*4]);
                    ull p2 = pack1f(p.x);
                    oacc2[0] = fma2(p2, v.x, oacc2[0]); oacc2[1] = fma2(p2, v.y, oacc2[1]);
                }
                {
                    ulonglong2 v = *reinterpret_cast<const ulonglong2*>(&Vs[(k4*4+1)*36 + pjg*4]);
                    ull p2 = pack1f(p.y);
                    oacc2[0] = fma2(p2, v.x, oacc2[0]); oacc2[1] = fma2(p2, v.y, oacc2[1]);
                }
                {
                    ulonglong2 v = *reinterpret_cast<const ulonglong2*>(&Vs[(k4*4+2)*36 + pjg*4]);
                    ull p2 = pack1f(p.z);
                    oacc2[0] = fma2(p2, v.x, oacc2[0]); oacc2[1] = fma2(p2, v.y, oacc2[1]);
                }
                {
                    ulonglong2 v = *reinterpret_cast<const ulonglong2*>(&Vs[(k4*4+3)*36 + pjg*4]);
                    ull p2 = pack1f(p.w);
                    oacc2[0] = fma2(p2, v.x, oacc2[0]); oacc2[1] = fma2(p2, v.y, oacc2[1]);
                }
            }
        }
    }

    __syncthreads();
    float inv = 1.f / lS[pq];
    float o0, o1, o2v, o3;
    unpack2f(oacc2[0], o0, o1);
    unpack2f(oacc2[1], o2v, o3);
    float4 ov = make_float4(o0*inv, o1*inv, o2v*inv, o3*inv);
    reinterpret_cast<float4*>(g_o + ((b*NWIN+w)*TQ + pq)*CC + h*DD)[pjg] = ov;
}

extern "C" void kernel_launch(void* const* d_in, const int* in_sizes, int n_in,
                              void* d_out, int out_size) {
    const float* feat  = (const float*)d_in[0];
    const float* qkv_w = (const float*)d_in[1];
    const float* qkv_b = (const float*)d_in[2];
    const float* out_w = (const float*)d_in[3];
    const float* out_b = (const float*)d_in[4];
    const float* ln_w  = (const float*)d_in[5];
    const float* ln_b  = (const float*)d_in[6];
    float* out = (float*)d_out;

    ln_qtok_kernel<<<1024, 256>>>(feat, ln_w, ln_b);
    pool_kernel<<<2560, 256>>>(feat);
    gemm_kernel<0,128><<<dim3(4, 256), 256>>>(qkv_w, qkv_b, feat, nullptr);  // local KV
    gemm_kernel<1,64> <<<dim3(4, 64),  256>>>(qkv_w, qkv_b, feat, nullptr);  // Q proj
    gemm_kernel<2,64> <<<dim3(8, 20),  256>>>(qkv_w, qkv_b, feat, nullptr);  // pooled KV
    attn_kernel<<<dim3(256, 8, 2), 128>>>();
    gemm_kernel<3,64> <<<dim3(4, 64),  256>>>(out_w, out_b, feat, out);      // out proj + residual
}

// round 11
// speedup vs baseline: 1.3851x; 1.3667x over previous
#include <cuda_runtime.h>

typedef unsigned long long ull;

#define BB   2
#define CC   256
#define NH   8
#define DD   32
#define NWIN 256
#define TQ   16
#define LL   64
#define LM   1024
#define LG   256

// ---------- packed f32x2 helpers ----------
__device__ __forceinline__ ull pack2f(float x, float y) {
    ull d;
    asm("mov.b64 %0, {%1, %2};" : "=l"(d)
        : "r"(__float_as_uint(x)), "r"(__float_as_uint(y)));
    return d;
}
__device__ __forceinline__ ull pack1f(float x) { return pack2f(x, x); }
__device__ __forceinline__ ull fma2(ull a, ull b, ull c) {
    ull d;
    asm("fma.rn.f32x2 %0, %1, %2, %3;" : "=l"(d) : "l"(a), "l"(b), "l"(c));
    return d;
}
__device__ __forceinline__ ull mul2(ull a, ull b) {
    ull d;
    asm("mul.rn.f32x2 %0, %1, %2;" : "=l"(d) : "l"(a), "l"(b));
    return d;
}
__device__ __forceinline__ void unpack2f(ull v, float& x, float& y) {
    unsigned lo, hi;
    asm("mov.b64 {%0, %1}, %2;" : "=r"(lo), "=r"(hi) : "l"(v));
    x = __uint_as_float(lo); y = __uint_as_float(hi);
}

// ---------- tf32 mma helpers ----------
__device__ __forceinline__ float to_tf32(float x) {
    unsigned r; asm("cvt.rna.tf32.f32 %0, %1;" : "=r"(r) : "f"(x));
    return __uint_as_float(r);
}
__device__ __forceinline__ void mma8(float* c, unsigned a0, unsigned a1,
                                     unsigned a2, unsigned a3,
                                     unsigned b0, unsigned b1) {
    asm volatile("mma.sync.aligned.m16n8k8.row.col.f32.tf32.tf32.f32 "
                 "{%0,%1,%2,%3}, {%4,%5,%6,%7}, {%8,%9}, {%0,%1,%2,%3};"
                 : "+f"(c[0]), "+f"(c[1]), "+f"(c[2]), "+f"(c[3])
                 : "r"(a0), "r"(a1), "r"(a2), "r"(a3), "r"(b0), "r"(b1));
}

// ---------- device scratch ----------
__device__ __align__(16) float g_qtok[BB*NWIN*TQ*CC];
__device__ __align__(16) float g_q   [BB*NWIN*TQ*CC];
__device__ __align__(16) float g_pt  [CC*(BB*LM + BB*LG)];   // column-major [C][2560]
__device__ __align__(16) float g_kl  [BB*NWIN*NH*DD*LL];
__device__ __align__(16) float g_vl  [BB*NWIN*NH*LL*DD];
__device__ __align__(16) float g_km  [BB*NH*DD*LM];
__device__ __align__(16) float g_vm  [BB*NH*LM*DD];
__device__ __align__(16) float g_kg  [BB*NH*DD*LG];
__device__ __align__(16) float g_vg  [BB*NH*LG*DD];
__device__ __align__(16) float g_o   [BB*NWIN*TQ*CC];

// ---------- kernel 1: window scramble + LayerNorm ----------
__global__ void ln_qtok_kernel(const float* __restrict__ feat,
                               const float* __restrict__ lnw,
                               const float* __restrict__ lnb) {
    int gw   = (blockIdx.x * blockDim.x + threadIdx.x) >> 5;
    int lane = threadIdx.x & 31;
    if (gw >= BB*NWIN*TQ) return;
    int t = gw & 15, w = (gw >> 4) & 255, b = gw >> 12;
    int wy = w >> 4, wx = w & 15;
    float v[8];
#pragma unroll
    for (int e = 0; e < 8; e++) {
        int cp = e*32 + lane;
        int c  = t*16 + (cp >> 4);
        int s  = cp & 15;
        int y  = wy*4 + (s >> 2), x = wx*4 + (s & 3);
        v[e] = feat[((b*CC + c) << 12) + (y << 6) + x];
    }
    float sum = 0.f, sq = 0.f;
#pragma unroll
    for (int e = 0; e < 8; e++) { sum += v[e]; sq += v[e]*v[e]; }
#pragma unroll
    for (int o = 16; o; o >>= 1) {
        sum += __shfl_xor_sync(0xffffffffu, sum, o);
        sq  += __shfl_xor_sync(0xffffffffu, sq,  o);
    }
    float mean = sum * (1.f/256.f);
    float var  = sq  * (1.f/256.f) - mean*mean;
    float rstd = rsqrtf(var + 1e-5f);
    float* dst = g_qtok + gw*CC;
#pragma unroll
    for (int e = 0; e < 8; e++) {
        int cp = e*32 + lane;
        dst[cp] = (v[e]-mean)*rstd*lnw[cp] + lnb[cp];
    }
}

// ---------- kernel 2: pooling ----------
__global__ void pool_kernel(const float* __restrict__ feat) {
    int idx = blockIdx.x * blockDim.x + threadIdx.x;
    int c = idx / 2560;
    int r = idx - c*2560;
    float val;
    if (r < BB*LM) {
        int b = r >> 10, tk = r & 1023;
        int ym = tk >> 5, xm = tk & 31;
        const float* p = feat + ((b*CC + c) << 12) + (ym << 7) + (xm << 1);
        val = 0.25f * (p[0] + p[1] + p[64] + p[65]);
    } else {
        int r2 = r - BB*LM;
        int b = r2 >> 8, tk = r2 & 255;
        int yg = tk >> 4, xg = tk & 15;
        const float* p = feat + ((b*CC + c) << 12) + (yg << 8) + (xg << 2);
        float s = 0.f;
#pragma unroll
        for (int dy = 0; dy < 4; dy++)
#pragma unroll
            for (int dx = 0; dx < 4; dx++)
                s += p[dy*64 + dx];
        val = s * (1.f/16.f);
    }
    g_pt[c*2560 + r] = val;
}

// ---------- per-(m,n) epilogue scatter ----------
template<int MODE>
__device__ __forceinline__ void epi_store(int m, int n, float val,
                                          const float* __restrict__ bias,
                                          const float* __restrict__ feat,
                                          float* __restrict__ dout) {
    if constexpr (MODE == 0) {
        val += bias[256 + n];
        int b = m >> 14, rem = m & 16383;
        int w = rem >> 6, l = rem & 63;
        if (n < 256) {
            int h = n >> 5, d = n & 31;
            g_kl[(((b*NWIN + w)*NH + h)*DD + d)*LL + l] = val;
        } else {
            int n2 = n - 256, h = n2 >> 5, d = n2 & 31;
            g_vl[(((b*NWIN + w)*NH + h)*LL + l)*DD + d] = val;
        }
    } else if constexpr (MODE == 1) {
        g_q[m*256 + n] = val + bias[n];
    } else if constexpr (MODE == 2) {
        val += bias[256 + n];
        if (m < BB*LM) {
            int b = m >> 10, tk = m & 1023;
            if (n < 256) { int h=n>>5, d=n&31; g_km[((b*NH+h)*DD+d)*LM + tk] = val; }
            else { int n2=n-256, h=n2>>5, d=n2&31; g_vm[((b*NH+h)*LM+tk)*DD + d] = val; }
        } else {
            int m2 = m - BB*LM;
            int b = m2 >> 8, tk = m2 & 255;
            if (n < 256) { int h=n>>5, d=n&31; g_kg[((b*NH+h)*DD+d)*LG + tk] = val; }
            else { int n2=n-256, h=n2>>5, d=n2&31; g_vg[((b*NH+h)*LG+tk)*DD + d] = val; }
        }
    } else {
        val += bias[n];
        int b = m >> 12, rem = m & 4095;
        int w = rem >> 4, t = rem & 15;
        int y = (w >> 4)*4 + (t >> 2);
        int x = (w & 15)*4 + (t & 3);
        int idx = ((b*CC + n) << 12) + (y << 6) + x;
        dout[idx] = val + feat[idx];
    }
}

// ---------- tf32 mma GEMM: 128xNT tile, 256 threads (8 warps, 4m x 2n) ----------
// MODE 0: local KV (A gathered).  1: Q proj.  2: pooled KV.  3: out proj.
template<int MODE, int NT>
__global__ void __launch_bounds__(256) gemm_kernel(const float* __restrict__ Wm,
                                                   const float* __restrict__ bias,
                                                   const float* __restrict__ feat,
                                                   float* __restrict__ dout) {
    constexpr int LDA  = 132;
    constexpr int LDBS = NT + 4;
    __shared__ __align__(16) float As[8*LDA];
    __shared__ __align__(16) float Bs[8*LDBS];
    const int tid  = threadIdx.x;
    const int bcol = blockIdx.x, brow = blockIdx.y;
    constexpr int LDB  = (MODE == 3) ? 256 : 768;
    constexpr int COL0 = (MODE == 0 || MODE == 2) ? 256 : 0;
    const int m0 = brow * 128;

    const int warp = tid >> 5, lane = tid & 31;
    const int wm = warp & 3, wn = warp >> 2;      // 4 x 2 warp grid
    const int g = lane >> 2, t4 = lane & 3;
    constexpr int NWT = NT / 2;                   // n span per warp
    constexpr int NTL = NWT / 8;                  // n-tiles per warp (8 or 4)

    float acc[2][NTL][4];
#pragma unroll
    for (int mt = 0; mt < 2; mt++)
#pragma unroll
        for (int nt = 0; nt < NTL; nt++)
#pragma unroll
            for (int r = 0; r < 4; r++) acc[mt][nt][r] = 0.f;

    // loader thread mapping (same as before)
    const int arow = tid >> 1;
    const int ak4  = (tid & 1) << 2;
    const int bkr  = tid >> 5;
    const int bn   = (NT == 128) ? ((tid & 31) << 2) : ((tid & 31) << 1);
    const int am2  = (tid & 31) << 2;

    int gw_b = 0, gw_wy = 0, gw_wx = 0, gw_l = 0;
    if constexpr (MODE == 0) {
        int row = m0 + arow;
        gw_b = row >> 14;
        int rem = row & 16383;
        int w  = rem >> 6;
        gw_l  = rem & 63;
        gw_wy = w >> 4; gw_wx = w & 15;
    }

    float pa[4]; float pb[4];

    auto loadA = [&](int k0) {
        if constexpr (MODE == 2) {
            float4 av = *reinterpret_cast<const float4*>(g_pt + (k0+bkr)*2560 + m0 + am2);
            pa[0]=av.x; pa[1]=av.y; pa[2]=av.z; pa[3]=av.w;
        } else if constexpr (MODE == 0) {
#pragma unroll
            for (int i = 0; i < 4; i++) {
                int cp = k0 + ak4 + i;
                int c  = gw_l*4 + (cp >> 6);
                int s  = cp & 63;
                int y  = gw_wy*4 + (s >> 3) - 2;
                int x  = gw_wx*4 + (s & 7)  - 2;
                float v = 0.f;
                if ((unsigned)y < 64u && (unsigned)x < 64u)
                    v = feat[((gw_b*CC + c) << 12) + (y << 6) + x];
                pa[i] = v;
            }
        } else {
            const float* Aptr = (MODE == 1) ? g_qtok : g_o;
            float4 av = *reinterpret_cast<const float4*>(Aptr + (m0+arow)*256 + k0 + ak4);
            pa[0]=av.x; pa[1]=av.y; pa[2]=av.z; pa[3]=av.w;
        }
    };
    auto loadB = [&](int k0) {
        if constexpr (NT == 128) {
            float4 bv = *reinterpret_cast<const float4*>(Wm + (k0+bkr)*LDB + COL0 + bcol*128 + bn);
            pb[0]=bv.x; pb[1]=bv.y; pb[2]=bv.z; pb[3]=bv.w;
        } else {
            float2 bv = *reinterpret_cast<const float2*>(Wm + (k0+bkr)*LDB + COL0 + bcol*64 + bn);
            pb[0]=bv.x; pb[1]=bv.y;
        }
    };

    loadA(0); loadB(0);
    for (int k0 = 0; k0 < 256; k0 += 8) {
        // stage tile into smem, rounding to tf32
        if constexpr (MODE == 2) {
            *reinterpret_cast<float4*>(&As[bkr*LDA + am2]) =
                make_float4(to_tf32(pa[0]), to_tf32(pa[1]), to_tf32(pa[2]), to_tf32(pa[3]));
        } else {
            As[(ak4+0)*LDA + arow] = to_tf32(pa[0]);
            As[(ak4+1)*LDA + arow] = to_tf32(pa[1]);
            As[(ak4+2)*LDA + arow] = to_tf32(pa[2]);
            As[(ak4+3)*LDA + arow] = to_tf32(pa[3]);
        }
        if constexpr (NT == 128) {
            *reinterpret_cast<float4*>(&Bs[bkr*LDBS + bn]) =
                make_float4(to_tf32(pb[0]), to_tf32(pb[1]), to_tf32(pb[2]), to_tf32(pb[3]));
        } else {
            *reinterpret_cast<float2*>(&Bs[bkr*LDBS + bn]) =
                make_float2(to_tf32(pb[0]), to_tf32(pb[1]));
        }
        __syncthreads();
        if (k0 < 248) { loadA(k0+8); loadB(k0+8); }

        // A fragments: 2 m-tiles of 16 rows
        unsigned afr[2][4];
#pragma unroll
        for (int mt = 0; mt < 2; mt++) {
            int mb = wm*32 + mt*16 + g;
            afr[mt][0] = __float_as_uint(As[ t4   *LDA + mb    ]);
            afr[mt][1] = __float_as_uint(As[ t4   *LDA + mb + 8]);
            afr[mt][2] = __float_as_uint(As[(t4+4)*LDA + mb    ]);
            afr[mt][3] = __float_as_uint(As[(t4+4)*LDA + mb + 8]);
        }
#pragma unroll
        for (int nt = 0; nt < NTL; nt++) {
            int nb = wn*NWT + nt*8 + g;
            unsigned b0 = __float_as_uint(Bs[ t4   *LDBS + nb]);
            unsigned b1 = __float_as_uint(Bs[(t4+4)*LDBS + nb]);
            mma8(acc[0][nt], afr[0][0], afr[0][1], afr[0][2], afr[0][3], b0, b1);
            mma8(acc[1][nt], afr[1][0], afr[1][1], afr[1][2], afr[1][3], b0, b1);
        }
        __syncthreads();
    }

    // epilogue: C frag (q=g[+8], n=2*t4[+1])
#pragma unroll
    for (int mt = 0; mt < 2; mt++)
#pragma unroll
        for (int nt = 0; nt < NTL; nt++)
#pragma unroll
            for (int r = 0; r < 4; r++) {
                int m = m0 + wm*32 + mt*16 + g + ((r >> 1) << 3);
                int n = bcol*NT + wn*NWT + nt*8 + t4*2 + (r & 1);
                epi_store<MODE>(m, n, acc[mt][nt][r], bias, feat, dout);
            }
}

// ---------- fused flash attention: 1 CTA per (w,h,b), 128 threads, 11 chunks ----------
__global__ void __launch_bounds__(128) attn_kernel() {
    const int w = blockIdx.x, h = blockIdx.y, b = blockIdx.z;
    const int tid = threadIdx.x;
    __shared__ __align__(16) float qs_t[32][16];     // transposed q: [d][q]
    __shared__ __align__(16) float Ssm[16*132];
    __shared__ __align__(16) float Vs [128*36];

    {   // q tile, pre-scaled by 1/sqrt(d), transposed to [d][q]
        int t = tid >> 3, jv = tid & 7;
        float4 qv = reinterpret_cast<const float4*>(g_q + ((b*NWIN+w)*TQ + t)*CC + h*DD)[jv];
        const float sc = 0.1767766952966369f;
        qs_t[jv*4+0][t] = qv.x*sc; qs_t[jv*4+1][t] = qv.y*sc;
        qs_t[jv*4+2][t] = qv.z*sc; qs_t[jv*4+3][t] = qv.w*sc;
    }

    float m_run = -1e30f, l_run = 0.f;               // replicated per 8-thread q-group
    ull oacc2[2] = {0ull, 0ull};
    const int pq = tid >> 3, pjg = tid & 7;

    for (int ch = 0; ch < 11; ch++) {
        const float* Kp; const float* Vp; int Lk, kbase, cn;
        if (ch == 0) {
            Kp = g_kl + (((b*NWIN + w)*NH + h)*DD)*LL;
            Vp = g_vl + (((b*NWIN + w)*NH + h)*LL)*DD;
            Lk = LL; kbase = 0; cn = 64;
        } else if (ch <= 8) {
            Kp = g_km + ((b*NH + h)*DD)*LM;
            Vp = g_vm + ((b*NH + h)*LM)*DD;
            Lk = LM; kbase = (ch-1)*128; cn = 128;
        } else {
            Kp = g_kg + ((b*NH + h)*DD)*LG;
            Vp = g_vg + ((b*NH + h)*LG)*DD;
            Lk = LG; kbase = (ch-9)*128; cn = 128;
        }

        __syncthreads();   // prev PV finished with Ssm/Vs; qs_t visible on iter 0

        // -------- scores: one key per thread; RAW scores -> Ssm --------
        float s[16];
        if (tid < cn) {
            float kreg[32];
#pragma unroll
            for (int j = 0; j < 32; j++) kreg[j] = Kp[j*Lk + kbase + tid];
            ull a2[8];
#pragma unroll
            for (int qp = 0; qp < 8; qp++) a2[qp] = 0ull;
#pragma unroll
            for (int d = 0; d < 32; d++) {
                ull kd2 = pack1f(kreg[d]);
                ulonglong2 qa = *reinterpret_cast<const ulonglong2*>(&qs_t[d][0]);
                ulonglong2 qb = *reinterpret_cast<const ulonglong2*>(&qs_t[d][4]);
                ulonglong2 qc = *reinterpret_cast<const ulonglong2*>(&qs_t[d][8]);
                ulonglong2 qd = *reinterpret_cast<const ulonglong2*>(&qs_t[d][12]);
                a2[0] = fma2(kd2, qa.x, a2[0]); a2[1] = fma2(kd2, qa.y, a2[1]);
                a2[2] = fma2(kd2, qb.x, a2[2]); a2[3] = fma2(kd2, qb.y, a2[3]);
                a2[4] = fma2(kd2, qc.x, a2[4]); a2[5] = fma2(kd2, qc.y, a2[5]);
                a2[6] = fma2(kd2, qd.x, a2[6]); a2[7] = fma2(kd2, qd.y, a2[7]);
            }
#pragma unroll
            for (int qp = 0; qp < 8; qp++) unpack2f(a2[qp], s[2*qp], s[2*qp+1]);
        } else {
#pragma unroll
            for (int q = 0; q < 16; q++) s[q] = -1e30f;
        }
#pragma unroll
        for (int q = 0; q < 16; q++) Ssm[q*132 + tid] = s[q];

        // stage V chunk into padded smem [kk][d] (stride 36 floats)
        {
            const float4* V4 = reinterpret_cast<const float4*>(Vp + kbase*DD);
#pragma unroll
            for (int i = 0; i < 8; i++) {
                int e  = tid + i*128;
                int kk = e >> 3, jv = e & 7;
                float4 v;
                if (kk < cn) v = V4[kk*8 + jv];
                else         v = make_float4(0.f, 0.f, 0.f, 0.f);
                reinterpret_cast<float4*>(Vs)[kk*9 + jv] = v;
            }
        }

        __syncthreads();   // raw scores + Vs visible

        // -------- softmax in (pq,pjg) layout: 16 keys per thread --------
        {
            float4* Srow = reinterpret_cast<float4*>(Ssm) + pq*33 + pjg*4;
            float4 sv0 = Srow[0], sv1 = Srow[1], sv2 = Srow[2], sv3 = Srow[3];
            float mloc = fmaxf(fmaxf(fmaxf(sv0.x,sv0.y), fmaxf(sv0.z,sv0.w)),
                               fmaxf(fmaxf(sv1.x,sv1.y), fmaxf(sv1.z,sv1.w)));
            mloc = fmaxf(mloc, fmaxf(fmaxf(fmaxf(sv2.x,sv2.y), fmaxf(sv2.z,sv2.w)),
                                     fmaxf(fmaxf(sv3.x,sv3.y), fmaxf(sv3.z,sv3.w))));
#pragma unroll
            for (int o = 1; o < 8; o <<= 1)
                mloc = fmaxf(mloc, __shfl_xor_sync(0xffffffffu, mloc, o));
            float mn = fmaxf(m_run, mloc);
            float alpha = __expf(m_run - mn);
            sv0.x=__expf(sv0.x-mn); sv0.y=__expf(sv0.y-mn); sv0.z=__expf(sv0.z-mn); sv0.w=__expf(sv0.w-mn);
            sv1.x=__expf(sv1.x-mn); sv1.y=__expf(sv1.y-mn); sv1.z=__expf(sv1.z-mn); sv1.w=__expf(sv1.w-mn);
            sv2.x=__expf(sv2.x-mn); sv2.y=__expf(sv2.y-mn); sv2.z=__expf(sv2.z-mn); sv2.w=__expf(sv2.w-mn);
            sv3.x=__expf(sv3.x-mn); sv3.y=__expf(sv3.y-mn); sv3.z=__expf(sv3.z-mn); sv3.w=__expf(sv3.w-mn);
            Srow[0]=sv0; Srow[1]=sv1; Srow[2]=sv2; Srow[3]=sv3;
            float ssum = (sv0.x+sv0.y+sv0.z+sv0.w) + (sv1.x+sv1.y+sv1.z+sv1.w)
                       + (sv2.x+sv2.y+sv2.z+sv2.w) + (sv3.x+sv3.y+sv3.z+sv3.w);
#pragma unroll
            for (int o = 1; o < 8; o <<= 1)
                ssum += __shfl_xor_sync(0xffffffffu, ssum, o);
            l_run = l_run*alpha + ssum;
            m_run = mn;
            ull a2p = pack1f(alpha);
            oacc2[0] = mul2(oacc2[0], a2p);
            oacc2[1] = mul2(oacc2[1], a2p);
        }

        __syncthreads();   // full P rows visible

        // -------- PV: packed d-pairs; oacc2 covers d = pjg*4 .. +3 --------
        {
            const float4* S4 = reinterpret_cast<const float4*>(Ssm) + pq*33;
#pragma unroll 4
            for (int k4 = 0; k4 < 32; k4++) {
                float4 p = S4[k4];
                {
                    ulonglong2 v = *reinterpret_cast<const ulonglong2*>(&Vs[(k4*4+0)*36 + pjg*4]);
                    ull p2 = pack1f(p.x);
                    oacc2[0] = fma2(p2, v.x, oacc2[0]); oacc2[1] = fma2(p2, v.y, oacc2[1]);
                }
                {
                    ulonglong2 v = *reinterpret_cast<const ulonglong2*>(&Vs[(k4*4+1)*36 + pjg*4]);
                    ull p2 = pack1f(p.y);
                    oacc2[0] = fma2(p2, v.x, oacc2[0]); oacc2[1] = fma2(p2, v.y, oacc2[1]);
                }
                {
                    ulonglong2 v = *reinterpret_cast<const ulonglong2*>(&Vs[(k4*4+2)*36 + pjg*4]);
                    ull p2 = pack1f(p.z);
                    oacc2[0] = fma2(p2, v.x, oacc2[0]); oacc2[1] = fma2(p2, v.y, oacc2[1]);
                }
                {
                    ulonglong2 v = *reinterpret_cast<const ulonglong2*>(&Vs[(k4*4+3)*36 + pjg*4]);
                    ull p2 = pack1f(p.w);
                    oacc2[0] = fma2(p2, v.x, oacc2[0]); oacc2[1] = fma2(p2, v.y, oacc2[1]);
                }
            }
        }
    }

    float inv = 1.f / l_run;
    float o0, o1, o2v, o3;
    unpack2f(oacc2[0], o0, o1);
    unpack2f(oacc2[1], o2v, o3);
    float4 ov = make_float4(o0*inv, o1*inv, o2v*inv, o3*inv);
    reinterpret_cast<float4*>(g_o + ((b*NWIN+w)*TQ + pq)*CC + h*DD)[pjg] = ov;
}

extern "C" void kernel_launch(void* const* d_in, const int* in_sizes, int n_in,
                              void* d_out, int out_size) {
    const float* feat  = (const float*)d_in[0];
    const float* qkv_w = (const float*)d_in[1];
    const float* qkv_b = (const float*)d_in[2];
    const float* out_w = (const float*)d_in[3];
    const float* out_b = (const float*)d_in[4];
    const float* ln_w  = (const float*)d_in[5];
    const float* ln_b  = (const float*)d_in[6];
    float* out = (float*)d_out;

    ln_qtok_kernel<<<1024, 256>>>(feat, ln_w, ln_b);
    pool_kernel<<<2560, 256>>>(feat);
    gemm_kernel<0,128><<<dim3(4, 256), 256>>>(qkv_w, qkv_b, feat, nullptr);  // local KV
    gemm_kernel<1,64> <<<dim3(4, 64),  256>>>(qkv_w, qkv_b, feat, nullptr);  // Q proj
    gemm_kernel<2,64> <<<dim3(8, 20),  256>>>(qkv_w, qkv_b, feat, nullptr);  // pooled KV
    attn_kernel<<<dim3(256, 8, 2), 128>>>();
    gemm_kernel<3,64> <<<dim3(4, 64),  256>>>(out_w, out_b, feat, out);      // out proj + residual
}

// round 16
// speedup vs baseline: 1.9373x; 1.3986x over previous
#include <cuda_runtime.h>

typedef unsigned long long ull;

#define BB   2
#define CC   256
#define NH   8
#define DD   32
#define NWIN 256
#define TQ   16
#define LL   64
#define LM   1024
#define LG   256

// ---------- tf32 mma helpers ----------
__device__ __forceinline__ float to_tf32(float x) {
    unsigned r; asm("cvt.rna.tf32.f32 %0, %1;" : "=r"(r) : "f"(x));
    return __uint_as_float(r);
}
__device__ __forceinline__ void mma8(float* c, unsigned a0, unsigned a1,
                                     unsigned a2, unsigned a3,
                                     unsigned b0, unsigned b1) {
    asm volatile("mma.sync.aligned.m16n8k8.row.col.f32.tf32.tf32.f32 "
                 "{%0,%1,%2,%3}, {%4,%5,%6,%7}, {%8,%9}, {%0,%1,%2,%3};"
                 : "+f"(c[0]), "+f"(c[1]), "+f"(c[2]), "+f"(c[3])
                 : "r"(a0), "r"(a1), "r"(a2), "r"(a3), "r"(b0), "r"(b1));
}

// ---------- device scratch ----------
__device__ __align__(16) float g_qtok[BB*NWIN*TQ*CC];
__device__ __align__(16) float g_q   [BB*NWIN*TQ*CC];
__device__ __align__(16) float g_pt  [CC*(BB*LM + BB*LG)];   // column-major [C][2560]
__device__ __align__(16) float g_kl  [BB*NWIN*NH*DD*LL];
__device__ __align__(16) float g_vl  [BB*NWIN*NH*LL*DD];
__device__ __align__(16) float g_km  [BB*NH*DD*LM];
__device__ __align__(16) float g_vm  [BB*NH*LM*DD];
__device__ __align__(16) float g_kg  [BB*NH*DD*LG];
__device__ __align__(16) float g_vg  [BB*NH*LG*DD];
__device__ __align__(16) float g_o   [BB*NWIN*TQ*CC];

// ---------- kernel 1: window scramble + LayerNorm ----------
__global__ void ln_qtok_kernel(const float* __restrict__ feat,
                               const float* __restrict__ lnw,
                               const float* __restrict__ lnb) {
    int gw   = (blockIdx.x * blockDim.x + threadIdx.x) >> 5;
    int lane = threadIdx.x & 31;
    if (gw >= BB*NWIN*TQ) return;
    int t = gw & 15, w = (gw >> 4) & 255, b = gw >> 12;
    int wy = w >> 4, wx = w & 15;
    float v[8];
#pragma unroll
    for (int e = 0; e < 8; e++) {
        int cp = e*32 + lane;
        int c  = t*16 + (cp >> 4);
        int s  = cp & 15;
        int y  = wy*4 + (s >> 2), x = wx*4 + (s & 3);
        v[e] = feat[((b*CC + c) << 12) + (y << 6) + x];
    }
    float sum = 0.f, sq = 0.f;
#pragma unroll
    for (int e = 0; e < 8; e++) { sum += v[e]; sq += v[e]*v[e]; }
#pragma unroll
    for (int o = 16; o; o >>= 1) {
        sum += __shfl_xor_sync(0xffffffffu, sum, o);
        sq  += __shfl_xor_sync(0xffffffffu, sq,  o);
    }
    float mean = sum * (1.f/256.f);
    float var  = sq  * (1.f/256.f) - mean*mean;
    float rstd = rsqrtf(var + 1e-5f);
    float* dst = g_qtok + gw*CC;
#pragma unroll
    for (int e = 0; e < 8; e++) {
        int cp = e*32 + lane;
        dst[cp] = (v[e]-mean)*rstd*lnw[cp] + lnb[cp];
    }
}

// ---------- kernel 2: pooling ----------
__global__ void pool_kernel(const float* __restrict__ feat) {
    int idx = blockIdx.x * blockDim.x + threadIdx.x;
    int c = idx / 2560;
    int r = idx - c*2560;
    float val;
    if (r < BB*LM) {
        int b = r >> 10, tk = r & 1023;
        int ym = tk >> 5, xm = tk & 31;
        const float* p = feat + ((b*CC + c) << 12) + (ym << 7) + (xm << 1);
        val = 0.25f * (p[0] + p[1] + p[64] + p[65]);
    } else {
        int r2 = r - BB*LM;
        int b = r2 >> 8, tk = r2 & 255;
        int yg = tk >> 4, xg = tk & 15;
        const float* p = feat + ((b*CC + c) << 12) + (yg << 8) + (xg << 2);
        float s = 0.f;
#pragma unroll
        for (int dy = 0; dy < 4; dy++)
#pragma unroll
            for (int dx = 0; dx < 4; dx++)
                s += p[dy*64 + dx];
        val = s * (1.f/16.f);
    }
    g_pt[c*2560 + r] = val;
}

// ---------- per-(m,n) epilogue scatter ----------
template<int MODE>
__device__ __forceinline__ void epi_store(int m, int n, float val,
                                          const float* __restrict__ bias,
                                          const float* __restrict__ feat,
                                          float* __restrict__ dout) {
    if constexpr (MODE == 0) {
        val += bias[256 + n];
        int b = m >> 14, rem = m & 16383;
        int w = rem >> 6, l = rem & 63;
        if (n < 256) {
            int h = n >> 5, d = n & 31;
            g_kl[(((b*NWIN + w)*NH + h)*DD + d)*LL + l] = val;
        } else {
            int n2 = n - 256, h = n2 >> 5, d = n2 & 31;
            g_vl[(((b*NWIN + w)*NH + h)*LL + l)*DD + d] = val;
        }
    } else if constexpr (MODE == 1) {
        g_q[m*256 + n] = val + bias[n];
    } else if constexpr (MODE == 2) {
        val += bias[256 + n];
        if (m < BB*LM) {
            int b = m >> 10, tk = m & 1023;
            if (n < 256) { int h=n>>5, d=n&31; g_km[((b*NH+h)*DD+d)*LM + tk] = val; }
            else { int n2=n-256, h=n2>>5, d=n2&31; g_vm[((b*NH+h)*LM+tk)*DD + d] = val; }
        } else {
            int m2 = m - BB*LM;
            int b = m2 >> 8, tk = m2 & 255;
            if (n < 256) { int h=n>>5, d=n&31; g_kg[((b*NH+h)*DD+d)*LG + tk] = val; }
            else { int n2=n-256, h=n2>>5, d=n2&31; g_vg[((b*NH+h)*LG+tk)*DD + d] = val; }
        }
    } else {
        val += bias[n];
        int b = m >> 12, rem = m & 4095;
        int w = rem >> 4, t = rem & 15;
        int y = (w >> 4)*4 + (t >> 2);
        int x = (w & 15)*4 + (t & 3);
        int idx = ((b*CC + n) << 12) + (y << 6) + x;
        dout[idx] = val + feat[idx];
    }
}

// ---------- tf32 mma GEMM: 128xNT tile, 256 threads (8 warps, 4m x 2n) ----------
template<int MODE, int NT>
__global__ void __launch_bounds__(256) gemm_kernel(const float* __restrict__ Wm,
                                                   const float* __restrict__ bias,
                                                   const float* __restrict__ feat,
                                                   float* __restrict__ dout) {
    constexpr int LDA  = 132;
    constexpr int LDBS = NT + 4;
    __shared__ __align__(16) float As[8*LDA];
    __shared__ __align__(16) float Bs[8*LDBS];
    const int tid  = threadIdx.x;
    const int bcol = blockIdx.x, brow = blockIdx.y;
    constexpr int LDB  = (MODE == 3) ? 256 : 768;
    constexpr int COL0 = (MODE == 0 || MODE == 2) ? 256 : 0;
    const int m0 = brow * 128;

    const int warp = tid >> 5, lane = tid & 31;
    const int wm = warp & 3, wn = warp >> 2;
    const int g = lane >> 2, t4 = lane & 3;
    constexpr int NWT = NT / 2;
    constexpr int NTL = NWT / 8;

    float acc[2][NTL][4];
#pragma unroll
    for (int mt = 0; mt < 2; mt++)
#pragma unroll
        for (int nt = 0; nt < NTL; nt++)
#pragma unroll
            for (int r = 0; r < 4; r++) acc[mt][nt][r] = 0.f;

    const int arow = tid >> 1;
    const int ak4  = (tid & 1) << 2;
    const int bkr  = tid >> 5;
    const int bn   = (NT == 128) ? ((tid & 31) << 2) : ((tid & 31) << 1);
    const int am2  = (tid & 31) << 2;

    int gw_b = 0, gw_wy = 0, gw_wx = 0, gw_l = 0;
    if constexpr (MODE == 0) {
        int row = m0 + arow;
        gw_b = row >> 14;
        int rem = row & 16383;
        int w  = rem >> 6;
        gw_l  = rem & 63;
        gw_wy = w >> 4; gw_wx = w & 15;
    }

    float pa[4]; float pb[4];

    auto loadA = [&](int k0) {
        if constexpr (MODE == 2) {
            float4 av = *reinterpret_cast<const float4*>(g_pt + (k0+bkr)*2560 + m0 + am2);
            pa[0]=av.x; pa[1]=av.y; pa[2]=av.z; pa[3]=av.w;
        } else if constexpr (MODE == 0) {
#pragma unroll
            for (int i = 0; i < 4; i++) {
                int cp = k0 + ak4 + i;
                int c  = gw_l*4 + (cp >> 6);
                int s  = cp & 63;
                int y  = gw_wy*4 + (s >> 3) - 2;
                int x  = gw_wx*4 + (s & 7)  - 2;
                float v = 0.f;
                if ((unsigned)y < 64u && (unsigned)x < 64u)
                    v = feat[((gw_b*CC + c) << 12) + (y << 6) + x];
                pa[i] = v;
            }
        } else {
            const float* Aptr = (MODE == 1) ? g_qtok : g_o;
            float4 av = *reinterpret_cast<const float4*>(Aptr + (m0+arow)*256 + k0 + ak4);
            pa[0]=av.x; pa[1]=av.y; pa[2]=av.z; pa[3]=av.w;
        }
    };
    auto loadB = [&](int k0) {
        if constexpr (NT == 128) {
            float4 bv = *reinterpret_cast<const float4*>(Wm + (k0+bkr)*LDB + COL0 + bcol*128 + bn);
            pb[0]=bv.x; pb[1]=bv.y; pb[2]=bv.z; pb[3]=bv.w;
        } else {
            float2 bv = *reinterpret_cast<const float2*>(Wm + (k0+bkr)*LDB + COL0 + bcol*64 + bn);
            pb[0]=bv.x; pb[1]=bv.y;
        }
    };

    loadA(0); loadB(0);
    for (int k0 = 0; k0 < 256; k0 += 8) {
        if constexpr (MODE == 2) {
            *reinterpret_cast<float4*>(&As[bkr*LDA + am2]) =
                make_float4(to_tf32(pa[0]), to_tf32(pa[1]), to_tf32(pa[2]), to_tf32(pa[3]));
        } else {
            As[(ak4+0)*LDA + arow] = to_tf32(pa[0]);
            As[(ak4+1)*LDA + arow] = to_tf32(pa[1]);
            As[(ak4+2)*LDA + arow] = to_tf32(pa[2]);
            As[(ak4+3)*LDA + arow] = to_tf32(pa[3]);
        }
        if constexpr (NT == 128) {
            *reinterpret_cast<float4*>(&Bs[bkr*LDBS + bn]) =
                make_float4(to_tf32(pb[0]), to_tf32(pb[1]), to_tf32(pb[2]), to_tf32(pb[3]));
        } else {
            *reinterpret_cast<float2*>(&Bs[bkr*LDBS + bn]) =
                make_float2(to_tf32(pb[0]), to_tf32(pb[1]));
        }
        __syncthreads();
        if (k0 < 248) { loadA(k0+8); loadB(k0+8); }

        unsigned afr[2][4];
#pragma unroll
        for (int mt = 0; mt < 2; mt++) {
            int mb = wm*32 + mt*16 + g;
            afr[mt][0] = __float_as_uint(As[ t4   *LDA + mb    ]);
            afr[mt][1] = __float_as_uint(As[ t4   *LDA + mb + 8]);
            afr[mt][2] = __float_as_uint(As[(t4+4)*LDA + mb    ]);
            afr[mt][3] = __float_as_uint(As[(t4+4)*LDA + mb + 8]);
        }
#pragma unroll
        for (int nt = 0; nt < NTL; nt++) {
            int nb = wn*NWT + nt*8 + g;
            unsigned b0 = __float_as_uint(Bs[ t4   *LDBS + nb]);
            unsigned b1 = __float_as_uint(Bs[(t4+4)*LDBS + nb]);
            mma8(acc[0][nt], afr[0][0], afr[0][1], afr[0][2], afr[0][3], b0, b1);
            mma8(acc[1][nt], afr[1][0], afr[1][1], afr[1][2], afr[1][3], b0, b1);
        }
        __syncthreads();
    }

#pragma unroll
    for (int mt = 0; mt < 2; mt++)
#pragma unroll
        for (int nt = 0; nt < NTL; nt++)
#pragma unroll
            for (int r = 0; r < 4; r++) {
                int m = m0 + wm*32 + mt*16 + g + ((r >> 1) << 3);
                int n = bcol*NT + wn*NWT + nt*8 + t4*2 + (r & 1);
                epi_store<MODE>(m, n, acc[mt][nt][r], bias, feat, dout);
            }
}

// ---------- mma flash attention: 1 CTA per (window-pair, h, b), 128 threads ----------
// Warps split keys (32 each of a 128-key chunk). Q/P/O handled as m16n8k8 frags.
__global__ void __launch_bounds__(128) attn_kernel() {
    const int wpair = blockIdx.x, h = blockIdx.y, b = blockIdx.z;
    const int w0 = wpair * 2;
    const int tid = threadIdx.x;
    const int wk = tid >> 5, lane = tid & 31;
    const int g = lane >> 2, t4 = lane & 3;

    __shared__ __align__(16) float sbuf[4*32*36];    // Psm [32][132] / Osm [4][32][36]
    __shared__ __align__(16) float redmax2[128];     // [row32][warp4]
    __shared__ __align__(16) float redsum2[128];
    __shared__ float lsm[32];
    constexpr int LDP = 132;
    float* Psm = sbuf;

    // ---- Q fragments (loaded once), pre-scaled ----
    const float sc = 0.1767766952966369f;
    unsigned qf[2][4][4];
#pragma unroll
    for (int wt = 0; wt < 2; wt++) {
        const float* Qb = g_q + ((b*NWIN + w0 + wt)*TQ)*CC + h*DD;
#pragma unroll
        for (int ks = 0; ks < 4; ks++) {
            qf[wt][ks][0] = __float_as_uint(Qb[ g   *CC + ks*8 + t4    ] * sc);
            qf[wt][ks][1] = __float_as_uint(Qb[(g+8)*CC + ks*8 + t4    ] * sc);
            qf[wt][ks][2] = __float_as_uint(Qb[ g   *CC + ks*8 + t4 + 4] * sc);
            qf[wt][ks][3] = __float_as_uint(Qb[(g+8)*CC + ks*8 + t4 + 4] * sc);
        }
    }

    float oacc[2][4][4];
#pragma unroll
    for (int wt = 0; wt < 2; wt++)
#pragma unroll
        for (int nt = 0; nt < 4; nt++)
#pragma unroll
            for (int r = 0; r < 4; r++) oacc[wt][nt][r] = 0.f;
    float m_run[2][2] = {{-1e30f,-1e30f},{-1e30f,-1e30f}};
    float l_run[2][2] = {{0.f,0.f},{0.f,0.f}};

    for (int ch = 0; ch < 11; ch++) {
        const float* Kp; const float* Vp; int Lk, keyw;
        if (ch == 0) {
            int wloc = w0 + (wk >> 1);
            Kp = g_kl + (((b*NWIN + wloc)*NH + h))*DD*LL;
            Vp = g_vl + (((b*NWIN + wloc)*NH + h))*LL*DD;
            Lk = LL; keyw = (wk & 1)*32;
        } else if (ch <= 8) {
            Kp = g_km + ((b*NH + h))*DD*LM;
            Vp = g_vm + ((b*NH + h))*LM*DD;
            Lk = LM; keyw = (ch-1)*128 + wk*32;
        } else {
            Kp = g_kg + ((b*NH + h))*DD*LG;
            Vp = g_vg + ((b*NH + h))*LG*DD;
            Lk = LG; keyw = (ch-9)*128 + wk*32;
        }

        // ---- QK^T: S frags (keys = warp's 32) ----
        float sf[2][4][4];
#pragma unroll
        for (int wt = 0; wt < 2; wt++)
#pragma unroll
            for (int nt = 0; nt < 4; nt++)
#pragma unroll
                for (int r = 0; r < 4; r++) sf[wt][nt][r] = 0.f;
#pragma unroll
        for (int ks = 0; ks < 4; ks++) {
            unsigned bf[4][2];
#pragma unroll
            for (int nt = 0; nt < 4; nt++) {
                bf[nt][0] = __float_as_uint(Kp[(ks*8 + t4    )*Lk + keyw + nt*8 + g]);
                bf[nt][1] = __float_as_uint(Kp[(ks*8 + t4 + 4)*Lk + keyw + nt*8 + g]);
            }
#pragma unroll
            for (int nt = 0; nt < 4; nt++) {
                mma8(sf[0][nt], qf[0][ks][0], qf[0][ks][1], qf[0][ks][2], qf[0][ks][3],
                     bf[nt][0], bf[nt][1]);
                mma8(sf[1][nt], qf[1][ks][0], qf[1][ks][1], qf[1][ks][2], qf[1][ks][3],
                     bf[nt][0], bf[nt][1]);
            }
        }
        if (ch == 0) {      // local chunk: window wt only attends its own warps' keys
            int own = wk >> 1;
#pragma unroll
            for (int wt = 0; wt < 2; wt++)
                if (wt != own)
#pragma unroll
                    for (int nt = 0; nt < 4; nt++)
#pragma unroll
                        for (int r = 0; r < 4; r++) sf[wt][nt][r] = -1e30f;
        }

        // ---- row max (warp-local then cross-warp via smem) ----
#pragma unroll
        for (int wt = 0; wt < 2; wt++) {
            float m0 = -1e30f, m1 = -1e30f;
#pragma unroll
            for (int nt = 0; nt < 4; nt++) {
                m0 = fmaxf(m0, fmaxf(sf[wt][nt][0], sf[wt][nt][1]));
                m1 = fmaxf(m1, fmaxf(sf[wt][nt][2], sf[wt][nt][3]));
            }
            m0 = fmaxf(m0, __shfl_xor_sync(0xffffffffu, m0, 1));
            m0 = fmaxf(m0, __shfl_xor_sync(0xffffffffu, m0, 2));
            m1 = fmaxf(m1, __shfl_xor_sync(0xffffffffu, m1, 1));
            m1 = fmaxf(m1, __shfl_xor_sync(0xffffffffu, m1, 2));
            if (t4 == 0) {
                redmax2[(wt*16 + g    )*4 + wk] = m0;
                redmax2[(wt*16 + g + 8)*4 + wk] = m1;
            }
        }
        __syncthreads();

        // ---- softmax: exp + P->smem + partial sums; scale O by alpha ----
        float alpha[2][2];
#pragma unroll
        for (int wt = 0; wt < 2; wt++) {
            float4 r0 = *reinterpret_cast<const float4*>(&redmax2[(wt*16 + g    )*4]);
            float4 r1 = *reinterpret_cast<const float4*>(&redmax2[(wt*16 + g + 8)*4]);
            float c0 = fmaxf(fmaxf(r0.x, r0.y), fmaxf(r0.z, r0.w));
            float c1 = fmaxf(fmaxf(r1.x, r1.y), fmaxf(r1.z, r1.w));
            float mn0 = fmaxf(m_run[wt][0], c0);
            float mn1 = fmaxf(m_run[wt][1], c1);
            alpha[wt][0] = __expf(m_run[wt][0] - mn0);
            alpha[wt][1] = __expf(m_run[wt][1] - mn1);
            m_run[wt][0] = mn0; m_run[wt][1] = mn1;
            float s0 = 0.f, s1 = 0.f;
#pragma unroll
            for (int nt = 0; nt < 4; nt++) {
                float p0 = __expf(sf[wt][nt][0] - mn0);
                float p1 = __expf(sf[wt][nt][1] - mn0);
                float p2 = __expf(sf[wt][nt][2] - mn1);
                float p3 = __expf(sf[wt][nt][3] - mn1);
                s0 += p0 + p1; s1 += p2 + p3;
                *reinterpret_cast<float2*>(&Psm[(wt*16 + g    )*LDP + keyw%32 + wk*32 + nt*8 + 2*t4]) = make_float2(p0, p1);
                *reinterpret_cast<float2*>(&Psm[(wt*16 + g + 8)*LDP + keyw%32 + wk*32 + nt*8 + 2*t4]) = make_float2(p2, p3);
                oacc[wt][nt][0] *= alpha[wt][0]; oacc[wt][nt][1] *= alpha[wt][0];
                oacc[wt][nt][2] *= alpha[wt][1]; oacc[wt][nt][3] *= alpha[wt][1];
            }
            s0 += __shfl_xor_sync(0xffffffffu, s0, 1);
            s0 += __shfl_xor_sync(0xffffffffu, s0, 2);
            s1 += __shfl_xor_sync(0xffffffffu, s1, 1);
            s1 += __shfl_xor_sync(0xffffffffu, s1, 2);
            if (t4 == 0) {
                redsum2[(wt*16 + g    )*4 + wk] = s0;
                redsum2[(wt*16 + g + 8)*4 + wk] = s1;
            }
        }
        __syncthreads();
#pragma unroll
        for (int wt = 0; wt < 2; wt++) {
            float4 r0 = *reinterpret_cast<const float4*>(&redsum2[(wt*16 + g    )*4]);
            float4 r1 = *reinterpret_cast<const float4*>(&redsum2[(wt*16 + g + 8)*4]);
            l_run[wt][0] = l_run[wt][0]*alpha[wt][0] + (r0.x + r0.y + r0.z + r0.w);
            l_run[wt][1] = l_run[wt][1]*alpha[wt][1] + (r1.x + r1.y + r1.z + r1.w);
        }

        // ---- PV: O += P(own keys) @ V(own keys) ----
#pragma unroll
        for (int ks = 0; ks < 4; ks++) {
            unsigned vb[4][2];
#pragma unroll
            for (int nd = 0; nd < 4; nd++) {
                vb[nd][0] = __float_as_uint(Vp[(keyw + ks*8 + t4    )*DD + nd*8 + g]);
                vb[nd][1] = __float_as_uint(Vp[(keyw + ks*8 + t4 + 4)*DD + nd*8 + g]);
            }
#pragma unroll
            for (int wt = 0; wt < 2; wt++) {
                unsigned af0 = __float_as_uint(Psm[(wt*16 + g    )*LDP + wk*32 + ks*8 + t4    ]);
                unsigned af1 = __float_as_uint(Psm[(wt*16 + g + 8)*LDP + wk*32 + ks*8 + t4    ]);
                unsigned af2 = __float_as_uint(Psm[(wt*16 + g    )*LDP + wk*32 + ks*8 + t4 + 4]);
                unsigned af3 = __float_as_uint(Psm[(wt*16 + g + 8)*LDP + wk*32 + ks*8 + t4 + 4]);
#pragma unroll
                for (int nd = 0; nd < 4; nd++)
                    mma8(oacc[wt][nd], af0, af1, af2, af3, vb[nd][0], vb[nd][1]);
            }
        }
    }

    __syncthreads();    // all PV reads of Psm done; reuse sbuf as Osm
    float* Osm = sbuf;  // [wk][32][36]
#pragma unroll
    for (int wt = 0; wt < 2; wt++)
#pragma unroll
        for (int nd = 0; nd < 4; nd++) {
            *reinterpret_cast<float2*>(&Osm[(wk*32 + wt*16 + g    )*36 + nd*8 + 2*t4]) =
                make_float2(oacc[wt][nd][0], oacc[wt][nd][1]);
            *reinterpret_cast<float2*>(&Osm[(wk*32 + wt*16 + g + 8)*36 + nd*8 + 2*t4]) =
                make_float2(oacc[wt][nd][2], oacc[wt][nd][3]);
        }
    if (wk == 0 && t4 == 0) {
        lsm[g     ] = l_run[0][0];
        lsm[g + 8 ] = l_run[0][1];
        lsm[g + 16] = l_run[1][0];
        lsm[g + 24] = l_run[1][1];
    }
    __syncthreads();
    {
        int r   = tid >> 2;          // 0..31 = wt*16 + q
        int seg = (tid & 3) * 8;
        float acc[8];
#pragma unroll
        for (int j = 0; j < 8; j++) acc[j] = 0.f;
#pragma unroll
        for (int ww = 0; ww < 4; ww++) {
            const float4* p = reinterpret_cast<const float4*>(&Osm[(ww*32 + r)*36 + seg]);
            float4 a = p[0], c = p[1];
            acc[0]+=a.x; acc[1]+=a.y; acc[2]+=a.z; acc[3]+=a.w;
            acc[4]+=c.x; acc[5]+=c.y; acc[6]+=c.z; acc[7]+=c.w;
        }
        float inv = 1.f / lsm[r];
        int wloc = w0 + (r >> 4), q = r & 15;
        float* dst = g_o + ((b*NWIN + wloc)*TQ + q)*CC + h*DD + seg;
        reinterpret_cast<float4*>(dst)[0] = make_float4(acc[0]*inv, acc[1]*inv, acc[2]*inv, acc[3]*inv);
        reinterpret_cast<float4*>(dst)[1] = make_float4(acc[4]*inv, acc[5]*inv, acc[6]*inv, acc[7]*inv);
    }
}

extern "C" void kernel_launch(void* const* d_in, const int* in_sizes, int n_in,
                              void* d_out, int out_size) {
    const float* feat  = (const float*)d_in[0];
    const float* qkv_w = (const float*)d_in[1];
    const float* qkv_b = (const float*)d_in[2];
    const float* out_w = (const float*)d_in[3];
    const float* out_b = (const float*)d_in[4];
    const float* ln_w  = (const float*)d_in[5];
    const float* ln_b  = (const float*)d_in[6];
    float* out = (float*)d_out;

    ln_qtok_kernel<<<1024, 256>>>(feat, ln_w, ln_b);
    pool_kernel<<<2560, 256>>>(feat);
    gemm_kernel<0,128><<<dim3(4, 256), 256>>>(qkv_w, qkv_b, feat, nullptr);  // local KV
    gemm_kernel<1,64> <<<dim3(4, 64),  256>>>(qkv_w, qkv_b, feat, nullptr);  // Q proj
    gemm_kernel<2,64> <<<dim3(8, 20),  256>>>(qkv_w, qkv_b, feat, nullptr);  // pooled KV
    attn_kernel<<<dim3(128, 8, 2), 128>>>();
    gemm_kernel<3,64> <<<dim3(4, 64),  256>>>(out_w, out_b, feat, out);      // out proj + residual
}

// round 17
// speedup vs baseline: 3.0231x; 1.5605x over previous
#include <cuda_runtime.h>

typedef unsigned long long ull;

#define BB   2
#define CC   256
#define NH   8
#define DD   32
#define NWIN 256
#define TQ   16
#define LL   64
#define LM   1024
#define LG   256

// ---------- tf32 mma helpers ----------
__device__ __forceinline__ float to_tf32(float x) {
    unsigned r; asm("cvt.rna.tf32.f32 %0, %1;" : "=r"(r) : "f"(x));
    return __uint_as_float(r);
}
__device__ __forceinline__ void mma8(float* c, unsigned a0, unsigned a1,
                                     unsigned a2, unsigned a3,
                                     unsigned b0, unsigned b1) {
    asm volatile("mma.sync.aligned.m16n8k8.row.col.f32.tf32.tf32.f32 "
                 "{%0,%1,%2,%3}, {%4,%5,%6,%7}, {%8,%9}, {%0,%1,%2,%3};"
                 : "+f"(c[0]), "+f"(c[1]), "+f"(c[2]), "+f"(c[3])
                 : "r"(a0), "r"(a1), "r"(a2), "r"(a3), "r"(b0), "r"(b1));
}

// ---------- device scratch ----------
__device__ __align__(16) float g_qtok[BB*NWIN*TQ*CC];
__device__ __align__(16) float g_q   [BB*NWIN*TQ*CC];
__device__ __align__(16) float g_pt  [CC*(BB*LM + BB*LG)];   // column-major [C][2560]
__device__ __align__(16) float g_kl  [BB*NWIN*NH*DD*LL];
__device__ __align__(16) float g_vl  [BB*NWIN*NH*LL*DD];
__device__ __align__(16) float g_km  [BB*NH*DD*LM];
__device__ __align__(16) float g_vm  [BB*NH*LM*DD];
__device__ __align__(16) float g_kg  [BB*NH*DD*LG];
__device__ __align__(16) float g_vg  [BB*NH*LG*DD];
__device__ __align__(16) float g_o   [BB*NWIN*TQ*CC];

// ---------- kernel 1: window scramble + LayerNorm ----------
__global__ void ln_qtok_kernel(const float* __restrict__ feat,
                               const float* __restrict__ lnw,
                               const float* __restrict__ lnb) {
    int gw   = (blockIdx.x * blockDim.x + threadIdx.x) >> 5;
    int lane = threadIdx.x & 31;
    if (gw >= BB*NWIN*TQ) return;
    int t = gw & 15, w = (gw >> 4) & 255, b = gw >> 12;
    int wy = w >> 4, wx = w & 15;
    float v[8];
#pragma unroll
    for (int e = 0; e < 8; e++) {
        int cp = e*32 + lane;
        int c  = t*16 + (cp >> 4);
        int s  = cp & 15;
        int y  = wy*4 + (s >> 2), x = wx*4 + (s & 3);
        v[e] = feat[((b*CC + c) << 12) + (y << 6) + x];
    }
    float sum = 0.f, sq = 0.f;
#pragma unroll
    for (int e = 0; e < 8; e++) { sum += v[e]; sq += v[e]*v[e]; }
#pragma unroll
    for (int o = 16; o; o >>= 1) {
        sum += __shfl_xor_sync(0xffffffffu, sum, o);
        sq  += __shfl_xor_sync(0xffffffffu, sq,  o);
    }
    float mean = sum * (1.f/256.f);
    float var  = sq  * (1.f/256.f) - mean*mean;
    float rstd = rsqrtf(var + 1e-5f);
    float* dst = g_qtok + gw*CC;
#pragma unroll
    for (int e = 0; e < 8; e++) {
        int cp = e*32 + lane;
        dst[cp] = (v[e]-mean)*rstd*lnw[cp] + lnb[cp];
    }
}

// ---------- kernel 2: pooling ----------
__global__ void pool_kernel(const float* __restrict__ feat) {
    int idx = blockIdx.x * blockDim.x + threadIdx.x;
    int c = idx / 2560;
    int r = idx - c*2560;
    float val;
    if (r < BB*LM) {
        int b = r >> 10, tk = r & 1023;
        int ym = tk >> 5, xm = tk & 31;
        const float* p = feat + ((b*CC + c) << 12) + (ym << 7) + (xm << 1);
        val = 0.25f * (p[0] + p[1] + p[64] + p[65]);
    } else {
        int r2 = r - BB*LM;
        int b = r2 >> 8, tk = r2 & 255;
        int yg = tk >> 4, xg = tk & 15;
        const float* p = feat + ((b*CC + c) << 12) + (yg << 8) + (xg << 2);
        float s = 0.f;
#pragma unroll
        for (int dy = 0; dy < 4; dy++)
#pragma unroll
            for (int dx = 0; dx < 4; dx++)
                s += p[dy*64 + dx];
        val = s * (1.f/16.f);
    }
    g_pt[c*2560 + r] = val;
}

// ---------- per-(m,n) epilogue scatter ----------
template<int MODE>
__device__ __forceinline__ void epi_store(int m, int n, float val,
                                          const float* __restrict__ bias,
                                          const float* __restrict__ feat,
                                          float* __restrict__ dout) {
    if constexpr (MODE == 0) {
        val += bias[256 + n];
        int b = m >> 14, rem = m & 16383;
        int w = rem >> 6, l = rem & 63;
        if (n < 256) {
            int h = n >> 5, d = n & 31;
            g_kl[(((b*NWIN + w)*NH + h)*DD + d)*LL + l] = val;
        } else {
            int n2 = n - 256, h = n2 >> 5, d = n2 & 31;
            g_vl[(((b*NWIN + w)*NH + h)*LL + l)*DD + d] = val;
        }
    } else if constexpr (MODE == 1) {
        g_q[m*256 + n] = val + bias[n];
    } else if constexpr (MODE == 2) {
        val += bias[256 + n];
        if (m < BB*LM) {
            int b = m >> 10, tk = m & 1023;
            if (n < 256) { int h=n>>5, d=n&31; g_km[((b*NH+h)*DD+d)*LM + tk] = val; }
            else { int n2=n-256, h=n2>>5, d=n2&31; g_vm[((b*NH+h)*LM+tk)*DD + d] = val; }
        } else {
            int m2 = m - BB*LM;
            int b = m2 >> 8, tk = m2 & 255;
            if (n < 256) { int h=n>>5, d=n&31; g_kg[((b*NH+h)*DD+d)*LG + tk] = val; }
            else { int n2=n-256, h=n2>>5, d=n2&31; g_vg[((b*NH+h)*LG+tk)*DD + d] = val; }
        }
    } else {
        val += bias[n];
        int b = m >> 12, rem = m & 4095;
        int w = rem >> 4, t = rem & 15;
        int y = (w >> 4)*4 + (t >> 2);
        int x = (w & 15)*4 + (t & 3);
        int idx = ((b*CC + n) << 12) + (y << 6) + x;
        dout[idx] = val + feat[idx];
    }
}

// ---------- tf32 mma GEMM: 128xNT tile, k-step 16, 2-stage smem, 1 barrier/step ----------
template<int MODE, int NT>
__global__ void __launch_bounds__(256) gemm_kernel(const float* __restrict__ Wm,
                                                   const float* __restrict__ bias,
                                                   const float* __restrict__ feat,
                                                   float* __restrict__ dout) {
    constexpr int LDA  = 132;
    constexpr int LDBS = NT + 4;
    __shared__ __align__(16) float As[2][16*LDA];
    __shared__ __align__(16) float Bs[2][16*LDBS];
    const int tid  = threadIdx.x;
    const int bcol = blockIdx.x, brow = blockIdx.y;
    constexpr int LDB  = (MODE == 3) ? 256 : 768;
    constexpr int COL0 = (MODE == 0 || MODE == 2) ? 256 : 0;
    const int m0 = brow * 128;

    const int warp = tid >> 5, lane = tid & 31;
    const int wm = warp & 3, wn = warp >> 2;
    const int g = lane >> 2, t4 = lane & 3;
    constexpr int NWT = NT / 2;
    constexpr int NTL = NWT / 8;

    float acc[2][NTL][4];
#pragma unroll
    for (int mt = 0; mt < 2; mt++)
#pragma unroll
        for (int nt = 0; nt < NTL; nt++)
#pragma unroll
            for (int r = 0; r < 4; r++) acc[mt][nt][r] = 0.f;

    const int arow = tid >> 1;
    const int ak4  = (tid & 1) << 2;
    const int bkr  = tid >> 5;                           // 0..7
    const int bn   = (NT == 128) ? ((tid & 31) << 2) : ((tid & 31) << 1);
    const int am2  = (tid & 31) << 2;

    int gw_b = 0, gw_wy = 0, gw_wx = 0, gw_l = 0;
    if constexpr (MODE == 0) {
        int row = m0 + arow;
        gw_b = row >> 14;
        int rem = row & 16383;
        int w  = rem >> 6;
        gw_l  = rem & 63;
        gw_wy = w >> 4; gw_wx = w & 15;
    }

    float pa[8]; float pb[8];

    auto loadA = [&](int k0) {                // 16-deep k tile into regs
        if constexpr (MODE == 2) {
            float4 a0 = *reinterpret_cast<const float4*>(g_pt + (k0+bkr  )*2560 + m0 + am2);
            float4 a1 = *reinterpret_cast<const float4*>(g_pt + (k0+bkr+8)*2560 + m0 + am2);
            pa[0]=a0.x; pa[1]=a0.y; pa[2]=a0.z; pa[3]=a0.w;
            pa[4]=a1.x; pa[5]=a1.y; pa[6]=a1.z; pa[7]=a1.w;
        } else if constexpr (MODE == 0) {
#pragma unroll
            for (int half = 0; half < 2; half++)
#pragma unroll
                for (int i = 0; i < 4; i++) {
                    int cp = k0 + half*8 + ak4 + i;
                    int c  = gw_l*4 + (cp >> 6);
                    int s  = cp & 63;
                    int y  = gw_wy*4 + (s >> 3) - 2;
                    int x  = gw_wx*4 + (s & 7)  - 2;
                    float v = 0.f;
                    if ((unsigned)y < 64u && (unsigned)x < 64u)
                        v = feat[((gw_b*CC + c) << 12) + (y << 6) + x];
                    pa[half*4+i] = v;
                }
        } else {
            const float* Aptr = (MODE == 1) ? g_qtok : g_o;
            float4 a0 = *reinterpret_cast<const float4*>(Aptr + (m0+arow)*256 + k0 + ak4);
            float4 a1 = *reinterpret_cast<const float4*>(Aptr + (m0+arow)*256 + k0 + 8 + ak4);
            pa[0]=a0.x; pa[1]=a0.y; pa[2]=a0.z; pa[3]=a0.w;
            pa[4]=a1.x; pa[5]=a1.y; pa[6]=a1.z; pa[7]=a1.w;
        }
    };
    auto loadB = [&](int k0) {
        if constexpr (NT == 128) {
            float4 b0 = *reinterpret_cast<const float4*>(Wm + (k0+bkr  )*LDB + COL0 + bcol*128 + bn);
            float4 b1 = *reinterpret_cast<const float4*>(Wm + (k0+bkr+8)*LDB + COL0 + bcol*128 + bn);
            pb[0]=b0.x; pb[1]=b0.y; pb[2]=b0.z; pb[3]=b0.w;
            pb[4]=b1.x; pb[5]=b1.y; pb[6]=b1.z; pb[7]=b1.w;
        } else {
            float2 b0 = *reinterpret_cast<const float2*>(Wm + (k0+bkr  )*LDB + COL0 + bcol*64 + bn);
            float2 b1 = *reinterpret_cast<const float2*>(Wm + (k0+bkr+8)*LDB + COL0 + bcol*64 + bn);
            pb[0]=b0.x; pb[1]=b0.y; pb[2]=b1.x; pb[3]=b1.y;
        }
    };
    auto store = [&](int st) {
        if constexpr (MODE == 2) {
            *reinterpret_cast<float4*>(&As[st][ bkr   *LDA + am2]) =
                make_float4(to_tf32(pa[0]), to_tf32(pa[1]), to_tf32(pa[2]), to_tf32(pa[3]));
            *reinterpret_cast<float4*>(&As[st][(bkr+8)*LDA + am2]) =
                make_float4(to_tf32(pa[4]), to_tf32(pa[5]), to_tf32(pa[6]), to_tf32(pa[7]));
        } else {
#pragma unroll
            for (int i = 0; i < 4; i++) {
                As[st][(ak4+i  )*LDA + arow] = to_tf32(pa[i]);
                As[st][(ak4+i+8)*LDA + arow] = to_tf32(pa[4+i]);
            }
        }
        if constexpr (NT == 128) {
            *reinterpret_cast<float4*>(&Bs[st][ bkr   *LDBS + bn]) =
                make_float4(to_tf32(pb[0]), to_tf32(pb[1]), to_tf32(pb[2]), to_tf32(pb[3]));
            *reinterpret_cast<float4*>(&Bs[st][(bkr+8)*LDBS + bn]) =
                make_float4(to_tf32(pb[4]), to_tf32(pb[5]), to_tf32(pb[6]), to_tf32(pb[7]));
        } else {
            *reinterpret_cast<float2*>(&Bs[st][ bkr   *LDBS + bn]) =
                make_float2(to_tf32(pb[0]), to_tf32(pb[1]));
            *reinterpret_cast<float2*>(&Bs[st][(bkr+8)*LDBS + bn]) =
                make_float2(to_tf32(pb[2]), to_tf32(pb[3]));
        }
    };

    loadA(0); loadB(0);
    store(0);
    __syncthreads();

    for (int s = 0; s < 16; s++) {
        const int st = s & 1;
        if (s < 15) { loadA((s+1)*16); loadB((s+1)*16); }   // overlap with compute
#pragma unroll
        for (int kf = 0; kf < 2; kf++) {
            unsigned afr[2][4];
#pragma unroll
            for (int mt = 0; mt < 2; mt++) {
                int mb = wm*32 + mt*16 + g;
                afr[mt][0] = __float_as_uint(As[st][(kf*8 + t4    )*LDA + mb    ]);
                afr[mt][1] = __float_as_uint(As[st][(kf*8 + t4    )*LDA + mb + 8]);
                afr[mt][2] = __float_as_uint(As[st][(kf*8 + t4 + 4)*LDA + mb    ]);
                afr[mt][3] = __float_as_uint(As[st][(kf*8 + t4 + 4)*LDA + mb + 8]);
            }
#pragma unroll
            for (int nt = 0; nt < NTL; nt++) {
                int nb = wn*NWT + nt*8 + g;
                unsigned b0 = __float_as_uint(Bs[st][(kf*8 + t4    )*LDBS + nb]);
                unsigned b1 = __float_as_uint(Bs[st][(kf*8 + t4 + 4)*LDBS + nb]);
                mma8(acc[0][nt], afr[0][0], afr[0][1], afr[0][2], afr[0][3], b0, b1);
                mma8(acc[1][nt], afr[1][0], afr[1][1], afr[1][2], afr[1][3], b0, b1);
            }
        }
        if (s < 15) store(st ^ 1);
        __syncthreads();
    }

#pragma unroll
    for (int mt = 0; mt < 2; mt++)
#pragma unroll
        for (int nt = 0; nt < NTL; nt++)
#pragma unroll
            for (int r = 0; r < 4; r++) {
                int m = m0 + wm*32 + mt*16 + g + ((r >> 1) << 3);
                int n = bcol*NT + wn*NWT + nt*8 + t4*2 + (r & 1);
                epi_store<MODE>(m, n, acc[mt][nt][r], bias, feat, dout);
            }
}

// ---------- mma flash attention: 1 CTA per (4 windows, h, b), 128 threads ----------
// 12 chunks: 2 local (warp wk <-> window wk, 32 keys each) + 8 mid + 2 glb.
__global__ void __launch_bounds__(128) attn_kernel() {
    const int wquad = blockIdx.x, h = blockIdx.y, b = blockIdx.z;
    const int w0 = wquad * 4;
    const int tid = threadIdx.x;
    const int wk = tid >> 5, lane = tid & 31;
    const int g = lane >> 4 ? 0 : 0, gg = lane >> 2, t4 = lane & 3;   // gg = group row
    constexpr int LDP = 132;

    __shared__ __align__(16) float sbuf[9216];     // Psm [64][132] / Osm [4][64][36]
    __shared__ __align__(16) float4 qsm[512];      // [wt][ks][lane]
    __shared__ __align__(16) float redmax2[256];   // [row64][warp4]
    __shared__ __align__(16) float redsum2[256];
    __shared__ float lsm[64];
    float* Psm = sbuf;

    // ---- Q fragments -> smem (warp wk stages window wk), pre-scaled ----
    {
        const float sc = 0.1767766952966369f;
        const float* Qb = g_q + ((b*NWIN + w0 + wk)*TQ)*CC + h*DD;
#pragma unroll
        for (int ks = 0; ks < 4; ks++) {
            float4 f;
            f.x = Qb[ gg   *CC + ks*8 + t4    ] * sc;
            f.y = Qb[(gg+8)*CC + ks*8 + t4    ] * sc;
            f.z = Qb[ gg   *CC + ks*8 + t4 + 4] * sc;
            f.w = Qb[(gg+8)*CC + ks*8 + t4 + 4] * sc;
            qsm[(wk*4 + ks)*32 + lane] = f;
        }
    }
    __syncthreads();

    float oacc[4][4][4];
#pragma unroll
    for (int wt = 0; wt < 4; wt++)
#pragma unroll
        for (int nt = 0; nt < 4; nt++)
#pragma unroll
            for (int r = 0; r < 4; r++) oacc[wt][nt][r] = 0.f;
    float m_run[4][2], l_run[4][2];
#pragma unroll
    for (int wt = 0; wt < 4; wt++) {
        m_run[wt][0] = m_run[wt][1] = -1e30f;
        l_run[wt][0] = l_run[wt][1] = 0.f;
    }

    for (int ch = 0; ch < 12; ch++) {
        const float* Kp; const float* Vp; int Lk, keyb;
        if (ch < 2) {
            int wloc = w0 + wk;
            Kp = g_kl + ((b*NWIN + wloc)*NH + h)*DD*LL;
            Vp = g_vl + ((b*NWIN + wloc)*NH + h)*LL*DD;
            Lk = LL; keyb = ch*32;
        } else if (ch < 10) {
            Kp = g_km + ((b*NH + h))*DD*LM;
            Vp = g_vm + ((b*NH + h))*LM*DD;
            Lk = LM; keyb = (ch-2)*128 + wk*32;
        } else {
            Kp = g_kg + ((b*NH + h))*DD*LG;
            Vp = g_vg + ((b*NH + h))*LG*DD;
            Lk = LG; keyb = (ch-10)*128 + wk*32;
        }
        const int colb = wk*32;

        // ---- QK^T ----
        float sf[4][4][4];
#pragma unroll
        for (int wt = 0; wt < 4; wt++)
#pragma unroll
            for (int nt = 0; nt < 4; nt++)
#pragma unroll
                for (int r = 0; r < 4; r++) sf[wt][nt][r] = 0.f;
#pragma unroll
        for (int ks = 0; ks < 4; ks++) {
            unsigned bf[4][2];
#pragma unroll
            for (int nt = 0; nt < 4; nt++) {
                bf[nt][0] = __float_as_uint(Kp[(ks*8 + t4    )*Lk + keyb + nt*8 + gg]);
                bf[nt][1] = __float_as_uint(Kp[(ks*8 + t4 + 4)*Lk + keyb + nt*8 + gg]);
            }
#pragma unroll
            for (int wt = 0; wt < 4; wt++) {
                float4 qv = qsm[(wt*4 + ks)*32 + lane];
                unsigned q0 = __float_as_uint(qv.x), q1 = __float_as_uint(qv.y);
                unsigned q2 = __float_as_uint(qv.z), q3 = __float_as_uint(qv.w);
#pragma unroll
                for (int nt = 0; nt < 4; nt++)
                    mma8(sf[wt][nt], q0, q1, q2, q3, bf[nt][0], bf[nt][1]);
            }
        }
        if (ch < 2) {      // local: window wt only attends warp wt's keys
#pragma unroll
            for (int wt = 0; wt < 4; wt++)
                if (wt != wk)
#pragma unroll
                    for (int nt = 0; nt < 4; nt++)
#pragma unroll
                        for (int r = 0; r < 4; r++) sf[wt][nt][r] = -1e30f;
        }

        // ---- row max: warp-local + cross-warp via smem ----
#pragma unroll
        for (int wt = 0; wt < 4; wt++) {
            float m0 = -1e30f, m1 = -1e30f;
#pragma unroll
            for (int nt = 0; nt < 4; nt++) {
                m0 = fmaxf(m0, fmaxf(sf[wt][nt][0], sf[wt][nt][1]));
                m1 = fmaxf(m1, fmaxf(sf[wt][nt][2], sf[wt][nt][3]));
            }
            m0 = fmaxf(m0, __shfl_xor_sync(0xffffffffu, m0, 1));
            m0 = fmaxf(m0, __shfl_xor_sync(0xffffffffu, m0, 2));
            m1 = fmaxf(m1, __shfl_xor_sync(0xffffffffu, m1, 1));
            m1 = fmaxf(m1, __shfl_xor_sync(0xffffffffu, m1, 2));
            if (t4 == 0) {
                redmax2[(wt*16 + gg    )*4 + wk] = m0;
                redmax2[(wt*16 + gg + 8)*4 + wk] = m1;
            }
        }
        __syncthreads();

        // ---- softmax: exp, P->smem, partial sums; scale O ----
        float alpha[4][2];
#pragma unroll
        for (int wt = 0; wt < 4; wt++) {
            float4 r0 = *reinterpret_cast<const float4*>(&redmax2[(wt*16 + gg    )*4]);
            float4 r1 = *reinterpret_cast<const float4*>(&redmax2[(wt*16 + gg + 8)*4]);
            float c0 = fmaxf(fmaxf(r0.x, r0.y), fmaxf(r0.z, r0.w));
            float c1 = fmaxf(fmaxf(r1.x, r1.y), fmaxf(r1.z, r1.w));
            float mn0 = fmaxf(m_run[wt][0], c0);
            float mn1 = fmaxf(m_run[wt][1], c1);
            alpha[wt][0] = __expf(m_run[wt][0] - mn0);
            alpha[wt][1] = __expf(m_run[wt][1] - mn1);
            m_run[wt][0] = mn0; m_run[wt][1] = mn1;
            float s0 = 0.f, s1 = 0.f;
#pragma unroll
            for (int nt = 0; nt < 4; nt++) {
                float p0 = __expf(sf[wt][nt][0] - mn0);
                float p1 = __expf(sf[wt][nt][1] - mn0);
                float p2 = __expf(sf[wt][nt][2] - mn1);
                float p3 = __expf(sf[wt][nt][3] - mn1);
                s0 += p0 + p1; s1 += p2 + p3;
                *reinterpret_cast<float2*>(&Psm[(wt*16 + gg    )*LDP + colb + nt*8 + 2*t4]) = make_float2(p0, p1);
                *reinterpret_cast<float2*>(&Psm[(wt*16 + gg + 8)*LDP + colb + nt*8 + 2*t4]) = make_float2(p2, p3);
                oacc[wt][nt][0] *= alpha[wt][0]; oacc[wt][nt][1] *= alpha[wt][0];
                oacc[wt][nt][2] *= alpha[wt][1]; oacc[wt][nt][3] *= alpha[wt][1];
            }
            s0 += __shfl_xor_sync(0xffffffffu, s0, 1);
            s0 += __shfl_xor_sync(0xffffffffu, s0, 2);
            s1 += __shfl_xor_sync(0xffffffffu, s1, 1);
            s1 += __shfl_xor_sync(0xffffffffu, s1, 2);
            if (t4 == 0) {
                redsum2[(wt*16 + gg    )*4 + wk] = s0;
                redsum2[(wt*16 + gg + 8)*4 + wk] = s1;
            }
        }
        __syncthreads();
#pragma unroll
        for (int wt = 0; wt < 4; wt++) {
            float4 r0 = *reinterpret_cast<const float4*>(&redsum2[(wt*16 + gg    )*4]);
            float4 r1 = *reinterpret_cast<const float4*>(&redsum2[(wt*16 + gg + 8)*4]);
            l_run[wt][0] = l_run[wt][0]*alpha[wt][0] + (r0.x + r0.y + r0.z + r0.w);
            l_run[wt][1] = l_run[wt][1]*alpha[wt][1] + (r1.x + r1.y + r1.z + r1.w);
        }

        // ---- PV: O += P(own cols) @ V(own keys) ----
#pragma unroll
        for (int ks = 0; ks < 4; ks++) {
            unsigned vb[4][2];
#pragma unroll
            for (int nd = 0; nd < 4; nd++) {
                vb[nd][0] = __float_as_uint(Vp[(keyb + ks*8 + t4    )*DD + nd*8 + gg]);
                vb[nd][1] = __float_as_uint(Vp[(keyb + ks*8 + t4 + 4)*DD + nd*8 + gg]);
            }
#pragma unroll
            for (int wt = 0; wt < 4; wt++) {
                unsigned af0 = __float_as_uint(Psm[(wt*16 + gg    )*LDP + colb + ks*8 + t4    ]);
                unsigned af1 = __float_as_uint(Psm[(wt*16 + gg + 8)*LDP + colb + ks*8 + t4    ]);
                unsigned af2 = __float_as_uint(Psm[(wt*16 + gg    )*LDP + colb + ks*8 + t4 + 4]);
                unsigned af3 = __float_as_uint(Psm[(wt*16 + gg + 8)*LDP + colb + ks*8 + t4 + 4]);
#pragma unroll
                for (int nd = 0; nd < 4; nd++)
                    mma8(oacc[wt][nd], af0, af1, af2, af3, vb[nd][0], vb[nd][1]);
            }
        }
        __syncthreads();   // PV reads of Psm complete before next chunk overwrites
    }

    // ---- cross-warp O reduction via smem (alias Psm buffer) ----
    float* Osm = sbuf;     // [wk][64][36]
#pragma unroll
    for (int wt = 0; wt < 4; wt++)
#pragma unroll
        for (int nd = 0; nd < 4; nd++) {
            *reinterpret_cast<float2*>(&Osm[(wk*64 + wt*16 + gg    )*36 + nd*8 + 2*t4]) =
                make_float2(oacc[wt][nd][0], oacc[wt][nd][1]);
            *reinterpret_cast<float2*>(&Osm[(wk*64 + wt*16 + gg + 8)*36 + nd*8 + 2*t4]) =
                make_float2(oacc[wt][nd][2], oacc[wt][nd][3]);
        }
    if (wk == 0 && t4 == 0) {
#pragma unroll
        for (int wt = 0; wt < 4; wt++) {
            lsm[wt*16 + gg    ] = l_run[wt][0];
            lsm[wt*16 + gg + 8] = l_run[wt][1];
        }
    }
    __syncthreads();
    {
        int r   = tid >> 1;              // 0..63 = wt*16 + q
        int seg = (tid & 1) * 16;
        float acc[16];
#pragma unroll
        for (int j = 0; j < 16; j++) acc[j] = 0.f;
#pragma unroll
        for (int ww = 0; ww < 4; ww++) {
            const float4* p = reinterpret_cast<const float4*>(&Osm[(ww*64 + r)*36 + seg]);
#pragma unroll
            for (int v = 0; v < 4; v++) {
                float4 a = p[v];
                acc[v*4+0]+=a.x; acc[v*4+1]+=a.y; acc[v*4+2]+=a.z; acc[v*4+3]+=a.w;
            }
        }
        float inv = 1.f / lsm[r];
        int wloc = w0 + (r >> 4), q = r & 15;
        float* dst = g_o + ((b*NWIN + wloc)*TQ + q)*CC + h*DD + seg;
#pragma unroll
        for (int v = 0; v < 4; v++)
            reinterpret_cast<float4*>(dst)[v] =
                make_float4(acc[v*4+0]*inv, acc[v*4+1]*inv, acc[v*4+2]*inv, acc[v*4+3]*inv);
    }
}

extern "C" void kernel_launch(void* const* d_in, const int* in_sizes, int n_in,
                              void* d_out, int out_size) {
    const float* feat  = (const float*)d_in[0];
    const float* qkv_w = (const float*)d_in[1];
    const float* qkv_b = (const float*)d_in[2];
    const float* out_w = (const float*)d_in[3];
    const float* out_b = (const float*)d_in[4];
    const float* ln_w  = (const float*)d_in[5];
    const float* ln_b  = (const float*)d_in[6];
    float* out = (float*)d_out;

    ln_qtok_kernel<<<1024, 256>>>(feat, ln_w, ln_b);
    pool_kernel<<<2560, 256>>>(feat);
    gemm_kernel<0,128><<<dim3(4, 256), 256>>>(qkv_w, qkv_b, feat, nullptr);  // local KV
    gemm_kernel<1,64> <<<dim3(4, 64),  256>>>(qkv_w, qkv_b, feat, nullptr);  // Q proj
    gemm_kernel<2,64> <<<dim3(8, 20),  256>>>(qkv_w, qkv_b, feat, nullptr);  // pooled KV
    attn_kernel<<<dim3(64, 8, 2), 128>>>();
    gemm_kernel<3,64> <<<dim3(4, 64),  256>>>(out_w, out_b, feat, out);      // out proj + residual
}